// round 2
// baseline (speedup 1.0000x reference)
#include <cuda_runtime.h>
#include <math.h>

#define B_    2
#define S_    2048
#define D_    1024
#define H_    16
#define HD_   64
#define NTOK  (B_*S_)        // 4096
#define E_    8
#define MROWS 9216           // 2*NTOK + 8*128 padding capacity
#define NTILES 72            // MROWS/128

// ---------------- device scratch (no cudaMalloc allowed) ----------------
__device__ float g_xn [NTOK*D_];
__device__ float g_q  [NTOK*D_];
__device__ float g_k  [NTOK*D_];
__device__ float g_v  [NTOK*D_];
__device__ float g_att[NTOK*D_];
__device__ float g_h  [NTOK*D_];
__device__ float g_xf [NTOK*D_];
__device__ float g_s1 [NTOK*D_];
__device__ float g_t  [NTOK*D_];
__device__ float g_sh [NTOK*D_];
__device__ float g_m1 [MROWS*D_];
__device__ float g_h1 [MROWS*D_];
__device__ float g_eo [MROWS*D_];
__device__ int   g_counts [E_];
__device__ int   g_cursor [E_];
__device__ int   g_padbase[E_+1];
__device__ int   g_tileE  [NTILES];
__device__ int   g_gather [MROWS];
__device__ int   g_tokE   [NTOK*2];
__device__ float g_tokW   [NTOK*2];
__device__ int   g_tokPos [NTOK*2];

// ---------------- rmsnorm ----------------
__global__ __launch_bounds__(256) void rmsnorm_k(const float* __restrict__ x,
                                                 const float* __restrict__ w,
                                                 float* __restrict__ y) {
    int n = blockIdx.x;
    const float* xr = x + (long)n * D_;
    float v[4]; float ss = 0.f;
    #pragma unroll
    for (int u = 0; u < 4; u++) { v[u] = xr[threadIdx.x + u*256]; ss += v[u]*v[u]; }
    __shared__ float red[256];
    red[threadIdx.x] = ss; __syncthreads();
    for (int s = 128; s > 0; s >>= 1) {
        if (threadIdx.x < s) red[threadIdx.x] += red[threadIdx.x + s];
        __syncthreads();
    }
    float r = rsqrtf(red[0] / (float)D_ + 1e-6f);
    float* yr = y + (long)n * D_;
    #pragma unroll
    for (int u = 0; u < 4; u++) { int c = threadIdx.x + u*256; yr[c] = v[u]*r*w[c]; }
}

// ---------------- RoPE (in-place on q and k) ----------------
__global__ __launch_bounds__(256) void rope_k(float* __restrict__ q, float* __restrict__ k,
                                              const float* __restrict__ fc,
                                              const float* __restrict__ fs) {
    int i = blockIdx.x * 256 + threadIdx.x;     // pair index, NTOK*512 total
    int n = i >> 9;
    int p = i & 511;
    int c = p * 2;
    int fi = (c & 63) >> 1;
    int s = n & (S_ - 1);
    float cc = fc[s*32 + fi], ssn = fs[s*32 + fi];
    long base = (long)n * D_ + c;
    float q0 = q[base], q1 = q[base+1];
    q[base]   = q0*cc - q1*ssn;
    q[base+1] = q0*ssn + q1*cc;
    float k0 = k[base], k1 = k[base+1];
    k[base]   = k0*cc - k1*ssn;
    k[base+1] = k0*ssn + k1*cc;
}

// ---------------- SGEMM 128x128x16, 8x8/thread ----------------
// EPI: 0 = C=acc ; 1 = C=acc+C2 ; 2 = C=acc*silu(C2)
template <int EPI>
__global__ __launch_bounds__(256) void sgemm_k(
    const float* __restrict__ A, const float* __restrict__ Bm,
    float* __restrict__ C, const float* __restrict__ C2,
    int K, int M,
    const int* __restrict__ gatherIdx,
    const int* __restrict__ tileExpert, long expertStride)
{
    __shared__ float As[16][132];
    __shared__ float Bs[16][128];
    const int tid = threadIdx.x, tx = tid & 15, ty = tid >> 4;
    const int row0 = blockIdx.y * 128, col0 = blockIdx.x * 128;
    const float* Bp = Bm;
    if (tileExpert) Bp += (long)tileExpert[blockIdx.y] * expertStride;

    float acc[8][8];
    #pragma unroll
    for (int i = 0; i < 8; i++)
        #pragma unroll
        for (int j = 0; j < 8; j++) acc[i][j] = 0.f;

    const int ar0 = tid >> 2;          // 0..63
    const int ak  = (tid & 3) * 4;     // 0,4,8,12
    const int br0 = tid >> 5;          // 0..7
    const int bc  = (tid & 31) * 4;

    for (int k0 = 0; k0 < K; k0 += 16) {
        #pragma unroll
        for (int u = 0; u < 2; u++) {
            int r = ar0 + u * 64;
            float4 av;
            if (gatherIdx) {
                int g = gatherIdx[row0 + r];
                if (g < 0) av = make_float4(0.f, 0.f, 0.f, 0.f);
                else       av = *(const float4*)(A + (long)g * K + k0 + ak);
            } else {
                av = *(const float4*)(A + (long)(row0 + r) * K + k0 + ak);
            }
            As[ak+0][r] = av.x; As[ak+1][r] = av.y;
            As[ak+2][r] = av.z; As[ak+3][r] = av.w;
        }
        #pragma unroll
        for (int u = 0; u < 2; u++) {
            int r = br0 + u * 8;
            *(float4*)(&Bs[r][bc]) = *(const float4*)(Bp + (long)(k0 + r) * M + col0 + bc);
        }
        __syncthreads();
        #pragma unroll
        for (int k = 0; k < 16; k++) {
            float4 a0 = *(const float4*)&As[k][ty*8];
            float4 a1 = *(const float4*)&As[k][ty*8+4];
            float4 b0 = *(const float4*)&Bs[k][tx*8];
            float4 b1 = *(const float4*)&Bs[k][tx*8+4];
            float a[8] = {a0.x,a0.y,a0.z,a0.w,a1.x,a1.y,a1.z,a1.w};
            float b[8] = {b0.x,b0.y,b0.z,b0.w,b1.x,b1.y,b1.z,b1.w};
            #pragma unroll
            for (int i = 0; i < 8; i++)
                #pragma unroll
                for (int j = 0; j < 8; j++)
                    acc[i][j] += a[i] * b[j];
        }
        __syncthreads();
    }
    #pragma unroll
    for (int i = 0; i < 8; i++) {
        int r = row0 + ty*8 + i;
        #pragma unroll
        for (int j = 0; j < 8; j++) {
            int c = col0 + tx*8 + j;
            long idx = (long)r * M + c;
            float v = acc[i][j];
            if (EPI == 1) v += C2[idx];
            else if (EPI == 2) { float s2 = C2[idx]; v *= s2 / (1.f + expf(-s2)); }
            C[idx] = v;
        }
    }
}

// ---------------- flash attention, 64 q-rows per block ----------------
// grid (S/64, B*H), 256 threads; dynamic smem 4*64*65 floats
__global__ __launch_bounds__(256) void flash_k(const float* __restrict__ q,
                                               const float* __restrict__ k,
                                               const float* __restrict__ v,
                                               float* __restrict__ o) {
    extern __shared__ float sm[];
    float* Qs = sm;
    float* Ks = sm + 64*65;
    float* Vs = sm + 2*64*65;
    float* Ps = sm + 3*64*65;
    int bh = blockIdx.y;
    int b = bh >> 4, h = bh & 15;
    int q0 = blockIdx.x * 64;
    int tid = threadIdx.x, tx = tid & 15, ty = tid >> 4;

    // load Q tile
    #pragma unroll
    for (int u = 0; u < 4; u++) {
        int f = tid + u*256; int r = f >> 4; int c = (f & 15) * 4;
        float4 val = *(const float4*)(q + ((long)b*S_ + q0 + r)*D_ + h*HD_ + c);
        Qs[r*65+c]=val.x; Qs[r*65+c+1]=val.y; Qs[r*65+c+2]=val.z; Qs[r*65+c+3]=val.w;
    }

    float m[4], l[4], O[4][4];
    #pragma unroll
    for (int i = 0; i < 4; i++) {
        m[i] = -1e30f; l[i] = 0.f;
        #pragma unroll
        for (int j = 0; j < 4; j++) O[i][j] = 0.f;
    }

    for (int kt = 0; kt < S_; kt += 64) {
        #pragma unroll
        for (int u = 0; u < 4; u++) {
            int f = tid + u*256; int r = f >> 4; int c = (f & 15) * 4;
            long gidx = ((long)b*S_ + kt + r)*D_ + h*HD_ + c;
            float4 kv = *(const float4*)(k + gidx);
            float4 vv = *(const float4*)(v + gidx);
            Ks[r*65+c]=kv.x; Ks[r*65+c+1]=kv.y; Ks[r*65+c+2]=kv.z; Ks[r*65+c+3]=kv.w;
            Vs[r*65+c]=vv.x; Vs[r*65+c+1]=vv.y; Vs[r*65+c+2]=vv.z; Vs[r*65+c+3]=vv.w;
        }
        __syncthreads();

        float s[4][4];
        #pragma unroll
        for (int i = 0; i < 4; i++)
            #pragma unroll
            for (int j = 0; j < 4; j++) s[i][j] = 0.f;

        for (int d = 0; d < 64; d++) {
            float a0=Qs[(ty*4+0)*65+d], a1=Qs[(ty*4+1)*65+d];
            float a2=Qs[(ty*4+2)*65+d], a3=Qs[(ty*4+3)*65+d];
            float b0=Ks[(tx*4+0)*65+d], b1=Ks[(tx*4+1)*65+d];
            float b2=Ks[(tx*4+2)*65+d], b3=Ks[(tx*4+3)*65+d];
            s[0][0]+=a0*b0; s[0][1]+=a0*b1; s[0][2]+=a0*b2; s[0][3]+=a0*b3;
            s[1][0]+=a1*b0; s[1][1]+=a1*b1; s[1][2]+=a1*b2; s[1][3]+=a1*b3;
            s[2][0]+=a2*b0; s[2][1]+=a2*b1; s[2][2]+=a2*b2; s[2][3]+=a2*b3;
            s[3][0]+=a3*b0; s[3][1]+=a3*b1; s[3][2]+=a3*b2; s[3][3]+=a3*b3;
        }

        #pragma unroll
        for (int i = 0; i < 4; i++) {
            #pragma unroll
            for (int j = 0; j < 4; j++) s[i][j] *= 0.125f;
            float rm = fmaxf(fmaxf(s[i][0], s[i][1]), fmaxf(s[i][2], s[i][3]));
            #pragma unroll
            for (int off = 1; off < 16; off <<= 1)
                rm = fmaxf(rm, __shfl_xor_sync(0xffffffffu, rm, off));
            float nm = fmaxf(m[i], rm);
            float alpha = expf(m[i] - nm);
            float rs = 0.f;
            #pragma unroll
            for (int j = 0; j < 4; j++) { s[i][j] = expf(s[i][j] - nm); rs += s[i][j]; }
            #pragma unroll
            for (int off = 1; off < 16; off <<= 1)
                rs += __shfl_xor_sync(0xffffffffu, rs, off);
            l[i] = l[i]*alpha + rs;
            m[i] = nm;
            #pragma unroll
            for (int j = 0; j < 4; j++) O[i][j] *= alpha;
            Ps[(ty*4+i)*65 + tx*4+0] = s[i][0];
            Ps[(ty*4+i)*65 + tx*4+1] = s[i][1];
            Ps[(ty*4+i)*65 + tx*4+2] = s[i][2];
            Ps[(ty*4+i)*65 + tx*4+3] = s[i][3];
        }
        __syncthreads();

        for (int kk = 0; kk < 64; kk++) {
            float p0=Ps[(ty*4+0)*65+kk], p1=Ps[(ty*4+1)*65+kk];
            float p2=Ps[(ty*4+2)*65+kk], p3=Ps[(ty*4+3)*65+kk];
            float v0=Vs[kk*65+tx*4+0], v1=Vs[kk*65+tx*4+1];
            float v2=Vs[kk*65+tx*4+2], v3=Vs[kk*65+tx*4+3];
            O[0][0]+=p0*v0; O[0][1]+=p0*v1; O[0][2]+=p0*v2; O[0][3]+=p0*v3;
            O[1][0]+=p1*v0; O[1][1]+=p1*v1; O[1][2]+=p1*v2; O[1][3]+=p1*v3;
            O[2][0]+=p2*v0; O[2][1]+=p2*v1; O[2][2]+=p2*v2; O[2][3]+=p2*v3;
            O[3][0]+=p3*v0; O[3][1]+=p3*v1; O[3][2]+=p3*v2; O[3][3]+=p3*v3;
        }
        __syncthreads();
    }

    #pragma unroll
    for (int i = 0; i < 4; i++) {
        float inv = 1.f / l[i];
        #pragma unroll
        for (int j = 0; j < 4; j++)
            o[((long)b*S_ + q0 + ty*4 + i)*D_ + h*HD_ + tx*4 + j] = O[i][j] * inv;
    }
}

// ---------------- MoE routing kernels ----------------
__global__ __launch_bounds__(256) void moe_init_k() {
    int i = blockIdx.x*256 + threadIdx.x;
    if (i < MROWS) g_gather[i] = -1;
    if (i < E_) { g_counts[i] = 0; g_cursor[i] = 0; }
}

__global__ __launch_bounds__(256) void gate_k(const float* __restrict__ xf,
                                              const float* __restrict__ gw) {
    int n = blockIdx.x;
    int tid = threadIdx.x, w = tid >> 5, lane = tid & 31;
    const float* xr = xf + (long)n * D_;
    const float* gr = gw + (long)w * D_;
    float s = 0.f;
    for (int d = lane; d < D_; d += 32) s += xr[d] * gr[d];
    #pragma unroll
    for (int o = 16; o; o >>= 1) s += __shfl_xor_sync(0xffffffffu, s, o);
    __shared__ float sc[E_];
    if (lane == 0) sc[w] = s;
    __syncthreads();
    if (tid == 0) {
        float mx = sc[0];
        for (int e = 1; e < E_; e++) mx = fmaxf(mx, sc[e]);
        float p[E_], sum = 0.f;
        for (int e = 0; e < E_; e++) { p[e] = expf(sc[e] - mx); sum += p[e]; }
        float inv = 1.f / sum;
        for (int e = 0; e < E_; e++) p[e] *= inv;
        int e0 = 0;
        for (int e = 1; e < E_; e++) if (p[e] > p[e0]) e0 = e;
        int e1 = (e0 == 0) ? 1 : 0;
        for (int e = 0; e < E_; e++) { if (e == e0) continue; if (p[e] > p[e1]) e1 = e; }
        float v0 = p[e0], v1 = p[e1];
        float wi = 1.f / (v0 + v1 + 1e-9f);
        g_tokE[2*n] = e0; g_tokE[2*n+1] = e1;
        g_tokW[2*n] = v0*wi; g_tokW[2*n+1] = v1*wi;
        atomicAdd(&g_counts[e0], 1);
        atomicAdd(&g_counts[e1], 1);
    }
}

__global__ void offsets_k() {
    if (threadIdx.x == 0) {
        int acc = 0;
        for (int e = 0; e < E_; e++) { g_padbase[e] = acc; acc += ((g_counts[e] + 127) >> 7) << 7; }
        g_padbase[E_] = acc;
    }
    __syncthreads();
    int t = threadIdx.x;
    if (t < NTILES) {
        int start = t * 128, te = 0;
        if (start < g_padbase[E_]) {
            for (int e = 0; e < E_; e++)
                if (start >= g_padbase[e] && start < g_padbase[e+1]) te = e;
        }
        g_tileE[t] = te;
    }
}

__global__ __launch_bounds__(256) void scatter_k() {
    int n = blockIdx.x*256 + threadIdx.x;
    if (n >= NTOK) return;
    #pragma unroll
    for (int kk = 0; kk < 2; kk++) {
        int e = g_tokE[2*n + kk];
        int slot = atomicAdd(&g_cursor[e], 1);
        int pos = g_padbase[e] + slot;
        g_gather[pos] = n;
        g_tokPos[2*n + kk] = pos;
    }
}

__global__ __launch_bounds__(256) void combine_k(float* __restrict__ out) {
    int i = blockIdx.x*256 + threadIdx.x;   // NTOK*D_ total
    int n = i >> 10, d = i & 1023;
    float v = g_h[i] + g_sh[i];
    v += g_tokW[2*n]   * g_eo[(long)g_tokPos[2*n]  * D_ + d];
    v += g_tokW[2*n+1] * g_eo[(long)g_tokPos[2*n+1]* D_ + d];
    out[i] = v;
}

// ---------------- host orchestration ----------------
extern "C" void kernel_launch(void* const* d_in, const int* in_sizes, int n_in,
                              void* d_out, int out_size) {
    const float* x   = (const float*)d_in[0];
    const float* fc  = (const float*)d_in[1];
    const float* fs  = (const float*)d_in[2];
    const float* anw = (const float*)d_in[3];
    const float* fnw = (const float*)d_in[4];
    const float* wq  = (const float*)d_in[5];
    const float* wk  = (const float*)d_in[6];
    const float* wv  = (const float*)d_in[7];
    const float* wo  = (const float*)d_in[8];
    const float* gw  = (const float*)d_in[9];
    const float* ew1 = (const float*)d_in[10];
    const float* ew2 = (const float*)d_in[11];
    const float* ew3 = (const float*)d_in[12];
    const float* sw1 = (const float*)d_in[13];
    const float* sw2 = (const float*)d_in[14];
    const float* sw3 = (const float*)d_in[15];
    float* out = (float*)d_out;

    float *xn,*q,*k,*v,*att,*h,*xf,*s1,*t,*sh,*m1,*h1,*eo;
    int *gath,*tileE;
    cudaGetSymbolAddress((void**)&xn,  g_xn);
    cudaGetSymbolAddress((void**)&q,   g_q);
    cudaGetSymbolAddress((void**)&k,   g_k);
    cudaGetSymbolAddress((void**)&v,   g_v);
    cudaGetSymbolAddress((void**)&att, g_att);
    cudaGetSymbolAddress((void**)&h,   g_h);
    cudaGetSymbolAddress((void**)&xf,  g_xf);
    cudaGetSymbolAddress((void**)&s1,  g_s1);
    cudaGetSymbolAddress((void**)&t,   g_t);
    cudaGetSymbolAddress((void**)&sh,  g_sh);
    cudaGetSymbolAddress((void**)&m1,  g_m1);
    cudaGetSymbolAddress((void**)&h1,  g_h1);
    cudaGetSymbolAddress((void**)&eo,  g_eo);
    cudaGetSymbolAddress((void**)&gath,  g_gather);
    cudaGetSymbolAddress((void**)&tileE, g_tileE);

    const long estride = (long)D_ * 1024;
    dim3 g32(8, 32), gmoe(8, NTILES);

    // attention path
    rmsnorm_k<<<NTOK, 256>>>(x, anw, xn);
    sgemm_k<0><<<g32, 256>>>(xn, wq, q, nullptr, D_, D_, nullptr, nullptr, 0);
    sgemm_k<0><<<g32, 256>>>(xn, wk, k, nullptr, D_, D_, nullptr, nullptr, 0);
    sgemm_k<0><<<g32, 256>>>(xn, wv, v, nullptr, D_, D_, nullptr, nullptr, 0);
    rope_k<<<(NTOK*512)/256, 256>>>(q, k, fc, fs);
    cudaFuncSetAttribute((const void*)flash_k,
                         cudaFuncAttributeMaxDynamicSharedMemorySize, 4*64*65*4);
    flash_k<<<dim3(S_/64, B_*H_), 256, 4*64*65*4>>>(q, k, v, att);
    sgemm_k<1><<<g32, 256>>>(att, wo, h, x, D_, D_, nullptr, nullptr, 0);

    // FFN path
    rmsnorm_k<<<NTOK, 256>>>(h, fnw, xf);
    sgemm_k<0><<<g32, 256>>>(xf, sw1, s1, nullptr, D_, 1024, nullptr, nullptr, 0);
    sgemm_k<2><<<g32, 256>>>(xf, sw3, t,  s1,      D_, 1024, nullptr, nullptr, 0);
    sgemm_k<0><<<g32, 256>>>(t,  sw2, sh, nullptr, 1024, D_, nullptr, nullptr, 0);

    // MoE routing
    moe_init_k<<<(MROWS + 255)/256, 256>>>();
    gate_k<<<NTOK, 256>>>(xf, gw);
    offsets_k<<<1, 128>>>();
    scatter_k<<<NTOK/256, 256>>>();

    // grouped expert GEMMs
    sgemm_k<0><<<gmoe, 256>>>(xf, ew1, m1, nullptr, D_, 1024, gath, tileE, estride);
    sgemm_k<2><<<gmoe, 256>>>(xf, ew3, h1, m1,      D_, 1024, gath, tileE, estride);
    sgemm_k<0><<<gmoe, 256>>>(h1, ew2, eo, nullptr, 1024, D_, nullptr, tileE, estride);

    // final combine: out = h + shared + sum_k w_k * eo[pos_k]
    combine_k<<<(NTOK*D_)/256, 256>>>(out);
}

// round 4
// speedup vs baseline: 5.2638x; 5.2638x over previous
#include <cuda_runtime.h>
#include <cuda_fp16.h>
#include <cstdint>
#include <math.h>

#define B_    2
#define S_    2048
#define D_    1024
#define H_    16
#define NTOK  4096
#define E_    8
#define MROWS 9216
#define NTILES 72

// ---------------- device scratch ----------------
__device__ float g_qkv[NTOK*3072];
__device__ float g_h  [NTOK*D_];
__device__ float g_xf [NTOK*D_];
__device__ float g_s1 [NTOK*D_];
__device__ float g_sh [NTOK*D_];
__device__ float g_m1 [MROWS*D_];
__device__ float g_eo [MROWS*D_];

__device__ __half g_xnh [NTOK*D_];
__device__ __half g_qh  [NTOK*D_];
__device__ __half g_kh  [NTOK*D_];
__device__ __half g_vh  [NTOK*D_];
__device__ __half g_atth[NTOK*D_];
__device__ __half g_xfh [NTOK*D_];
__device__ __half g_th  [NTOK*D_];
__device__ __half g_h1h [MROWS*D_];

__device__ __half g_wqkvh[D_*3072];
__device__ __half g_woh [D_*D_];
__device__ __half g_sw1h[D_*D_];
__device__ __half g_sw2h[D_*D_];
__device__ __half g_sw3h[D_*D_];
__device__ __half g_ew1h[E_*D_*D_];
__device__ __half g_ew2h[E_*D_*D_];
__device__ __half g_ew3h[E_*D_*D_];

__device__ int   g_counts [E_];
__device__ int   g_cursor [E_];
__device__ int   g_padbase[E_+1];
__device__ int   g_tileE  [NTILES];
__device__ int   g_gather [MROWS];
__device__ int   g_tokE   [NTOK*2];
__device__ float g_tokW   [NTOK*2];
__device__ int   g_tokPos [NTOK*2];

// ---------------- ptx helpers ----------------
__device__ __forceinline__ uint32_t sptr(const void* p){ return (uint32_t)__cvta_generic_to_shared(p); }
__device__ __forceinline__ void ldsm4(uint32_t* r, uint32_t a){
    asm volatile("ldmatrix.sync.aligned.m8n8.x4.shared.b16 {%0,%1,%2,%3},[%4];"
        :"=r"(r[0]),"=r"(r[1]),"=r"(r[2]),"=r"(r[3]):"r"(a));
}
__device__ __forceinline__ void ldsm4t(uint32_t* r, uint32_t a){
    asm volatile("ldmatrix.sync.aligned.m8n8.x4.trans.shared.b16 {%0,%1,%2,%3},[%4];"
        :"=r"(r[0]),"=r"(r[1]),"=r"(r[2]),"=r"(r[3]):"r"(a));
}
__device__ __forceinline__ void mma16816(float* c, const uint32_t* a, const uint32_t* b){
    asm volatile("mma.sync.aligned.m16n8k16.row.col.f32.f16.f16.f32 "
        "{%0,%1,%2,%3},{%4,%5,%6,%7},{%8,%9},{%0,%1,%2,%3};"
        :"+f"(c[0]),"+f"(c[1]),"+f"(c[2]),"+f"(c[3])
        :"r"(a[0]),"r"(a[1]),"r"(a[2]),"r"(a[3]),"r"(b[0]),"r"(b[1]));
}
__device__ __forceinline__ void cp16(uint32_t d, const void* s){
    asm volatile("cp.async.cg.shared.global [%0],[%1],16;"::"r"(d),"l"(s));
}
__device__ __forceinline__ void cpcommit(){ asm volatile("cp.async.commit_group;"); }
template<int N> __device__ __forceinline__ void cpwait(){ asm volatile("cp.async.wait_group %0;"::"n"(N)); }
__device__ __forceinline__ uint32_t packh2(float a, float b){
    __half2 h = __floats2half2_rn(a,b); return *(uint32_t*)&h;
}

// ---------------- conversions ----------------
__global__ __launch_bounds__(256) void cvt4_k(const float4* __restrict__ s, __half2* __restrict__ d, int n4){
    int i = blockIdx.x*256 + threadIdx.x;
    if (i < n4){ float4 v = s[i]; d[2*i] = __floats2half2_rn(v.x,v.y); d[2*i+1] = __floats2half2_rn(v.z,v.w); }
}
__global__ __launch_bounds__(256) void cvtqkv_k(const float* __restrict__ wq, const float* __restrict__ wk,
                                                const float* __restrict__ wv, __half* __restrict__ dst){
    int i = blockIdx.x*256 + threadIdx.x;      // over D_*D_
    int k = i >> 10, j = i & 1023;
    long o = (long)k*3072 + j;
    dst[o]        = __float2half(wq[i]);
    dst[o + 1024] = __float2half(wk[i]);
    dst[o + 2048] = __float2half(wv[i]);
}

// ---------------- rmsnorm (fp32 in, optional fp32 + half out) ----------------
__global__ __launch_bounds__(256) void rmsnorm_k(const float* __restrict__ x, const float* __restrict__ w,
                                                 float* __restrict__ yf, __half* __restrict__ yh){
    int n = blockIdx.x;
    const float* xr = x + (long)n * D_;
    float v[4]; float ss = 0.f;
    #pragma unroll
    for (int u = 0; u < 4; u++){ v[u] = xr[threadIdx.x + u*256]; ss += v[u]*v[u]; }
    __shared__ float red[256];
    red[threadIdx.x] = ss; __syncthreads();
    for (int s = 128; s > 0; s >>= 1){
        if (threadIdx.x < s) red[threadIdx.x] += red[threadIdx.x + s];
        __syncthreads();
    }
    float r = rsqrtf(red[0] / (float)D_ + 1e-6f);
    #pragma unroll
    for (int u = 0; u < 4; u++){
        int c = threadIdx.x + u*256;
        float val = v[u]*r*w[c];
        yh[(long)n*D_ + c] = __float2half(val);
        if (yf) yf[(long)n*D_ + c] = val;
    }
}

// ---------------- RoPE: qkv fp32 -> qh,kh,vh half ----------------
__global__ __launch_bounds__(256) void rope_k(const float* __restrict__ qkv,
                                              __half* __restrict__ qh, __half* __restrict__ kh, __half* __restrict__ vh,
                                              const float* __restrict__ fc, const float* __restrict__ fs){
    int i = blockIdx.x*256 + threadIdx.x;   // pair index, NTOK*512 total
    int n = i >> 9, p = i & 511;
    int c = p*2;
    int fi = (c & 63) >> 1;
    int s = n & (S_-1);
    float cc = fc[s*32 + fi], sn = fs[s*32 + fi];
    long gb = (long)n*3072 + c;
    long ob = (long)n*D_ + c;
    float q0 = qkv[gb], q1 = qkv[gb+1];
    *(__half2*)(qh + ob) = __floats2half2_rn(q0*cc - q1*sn, q0*sn + q1*cc);
    float k0 = qkv[gb+1024], k1 = qkv[gb+1025];
    *(__half2*)(kh + ob) = __floats2half2_rn(k0*cc - k1*sn, k0*sn + k1*cc);
    *(__half2*)(vh + ob) = __floats2half2_rn(qkv[gb+2048], qkv[gb+2049]);
}

// ---------------- HGEMM 128x128x32 double-buffered, mma.sync ----------------
#define ASTR 40
#define BSTR 136
template<typename OutT, int EPI>
__global__ __launch_bounds__(256) void hgemm_k(
    const __half* __restrict__ A, const __half* __restrict__ Bw,
    OutT* __restrict__ C, const float* __restrict__ C2,
    int K, int N,
    const int* __restrict__ gatherIdx, const int* __restrict__ tileExpert, long estride)
{
    __shared__ __half As[2][128*ASTR];
    __shared__ __half Bs[2][32*BSTR];
    const int tid = threadIdx.x, lane = tid & 31, wid = tid >> 5;
    const int wm = wid & 1, wn = wid >> 1;
    const int row0 = blockIdx.y*128, col0 = blockIdx.x*128;
    const __half* Bp = Bw + (tileExpert ? (long)tileExpert[blockIdx.y]*estride : 0);

    const int ar = tid >> 1, ac = tid & 1;
    long arow = 0; bool azero = false;
    if (gatherIdx){ int g = gatherIdx[row0 + ar]; if (g < 0) azero = true; else arow = (long)g*K; }
    else arow = (long)(row0 + ar)*K;
    const int br = tid >> 4, bc = tid & 15;

    float acc[4][4][4];
    #pragma unroll
    for (int a=0;a<4;a++)
        #pragma unroll
        for (int b=0;b<4;b++)
            #pragma unroll
            for (int c=0;c<4;c++) acc[a][b][c]=0.f;

    const int NIT = K >> 5;
    auto issue = [&](int it, int buf){
        int k0 = it << 5;
        #pragma unroll
        for (int u = 0; u < 2; u++){
            int c = ac + u*2;
            if (azero) *(uint4*)(&As[buf][ar*ASTR + c*8]) = make_uint4(0,0,0,0);
            else cp16(sptr(&As[buf][ar*ASTR + c*8]), A + arow + k0 + c*8);
        }
        #pragma unroll
        for (int u = 0; u < 2; u++){
            int r = br + u*16;
            cp16(sptr(&Bs[buf][r*BSTR + bc*8]), Bp + (long)(k0 + r)*N + col0 + bc*8);
        }
    };

    issue(0,0); cpcommit();
    for (int it = 0; it < NIT; ++it){
        int cur = it & 1;
        cpwait<0>(); __syncthreads();
        if (it+1 < NIT){ issue(it+1, cur^1); cpcommit(); }
        #pragma unroll
        for (int ks = 0; ks < 2; ++ks){
            uint32_t af[4][4];
            #pragma unroll
            for (int mf = 0; mf < 4; ++mf)
                ldsm4(af[mf], sptr(&As[cur][(wm*64 + mf*16 + (lane&15))*ASTR + ks*16 + (lane>>4)*8]));
            uint32_t bf[4][2];
            #pragma unroll
            for (int nf2 = 0; nf2 < 2; ++nf2){
                uint32_t r[4];
                ldsm4t(r, sptr(&Bs[cur][(ks*16 + (lane&15))*BSTR + wn*32 + nf2*16 + (lane>>4)*8]));
                bf[nf2*2][0]=r[0]; bf[nf2*2][1]=r[1]; bf[nf2*2+1][0]=r[2]; bf[nf2*2+1][1]=r[3];
            }
            #pragma unroll
            for (int mf = 0; mf < 4; ++mf)
                #pragma unroll
                for (int nt = 0; nt < 4; ++nt)
                    mma16816(acc[mf][nt], af[mf], bf[nt]);
        }
    }

    #pragma unroll
    for (int mf = 0; mf < 4; ++mf){
        int r = row0 + wm*64 + mf*16 + (lane>>2);
        #pragma unroll
        for (int nt = 0; nt < 4; ++nt){
            int c = col0 + wn*32 + nt*8 + (lane&3)*2;
            #pragma unroll
            for (int hh = 0; hh < 2; ++hh){
                long i = (long)(r + hh*8)*N + c;
                float v0 = acc[mf][nt][hh*2], v1 = acc[mf][nt][hh*2+1];
                if (EPI == 1){ float2 rr = *(const float2*)(C2 + i); v0 += rr.x; v1 += rr.y; }
                else if (EPI == 2){
                    float2 ss = *(const float2*)(C2 + i);
                    v0 *= ss.x / (1.f + __expf(-ss.x));
                    v1 *= ss.y / (1.f + __expf(-ss.y));
                }
                if (sizeof(OutT) == 2) *(__half2*)((__half*)C + i) = __floats2half2_rn(v0, v1);
                else { float2 w2; w2.x = v0; w2.y = v1; *(float2*)((float*)C + i) = w2; }
            }
        }
    }
}

// ---------------- flash attention fp16 (FA2-style), 64 q-rows / block ----------------
__global__ __launch_bounds__(128) void flash_h_k(const __half* __restrict__ qh, const __half* __restrict__ kh,
                                                 const __half* __restrict__ vh, __half* __restrict__ o){
    __shared__ __half Qs[64*72];
    __shared__ __half Ks[2][64*72];
    __shared__ __half Vs[2][64*72];
    const int tid = threadIdx.x, lane = tid & 31, w = tid >> 5;
    const int bh = blockIdx.y, b = bh >> 4, h = bh & 15;
    const int q0 = blockIdx.x*64;
    const int lrow = tid >> 1, lc0 = (tid & 1)*4;

    // load Q once
    {
        const __half* qb = qh + ((long)b*S_ + q0 + lrow)*D_ + h*64;
        #pragma unroll
        for (int c = 0; c < 4; c++)
            cp16(sptr(&Qs[lrow*72 + (lc0 + c)*8]), qb + (lc0 + c)*8);
        cpcommit();
    }
    auto issue_kv = [&](int kt, int buf){
        const __half* kb = kh + ((long)b*S_ + kt + lrow)*D_ + h*64;
        const __half* vb = vh + ((long)b*S_ + kt + lrow)*D_ + h*64;
        #pragma unroll
        for (int c = 0; c < 4; c++){
            cp16(sptr(&Ks[buf][lrow*72 + (lc0 + c)*8]), kb + (lc0 + c)*8);
            cp16(sptr(&Vs[buf][lrow*72 + (lc0 + c)*8]), vb + (lc0 + c)*8);
        }
    };
    issue_kv(0, 0); cpcommit();

    cpwait<1>(); __syncthreads();
    uint32_t aQ[4][4];
    #pragma unroll
    for (int ks = 0; ks < 4; ks++)
        ldsm4(aQ[ks], sptr(&Qs[(w*16 + (lane&15))*72 + ks*16 + (lane>>4)*8]));

    float oa[8][4];
    #pragma unroll
    for (int i = 0; i < 8; i++){ oa[i][0]=0.f; oa[i][1]=0.f; oa[i][2]=0.f; oa[i][3]=0.f; }
    float m0 = -1e30f, m1 = -1e30f, l0 = 0.f, l1 = 0.f;

    const int NKT = S_/64;
    for (int kti = 0; kti < NKT; ++kti){
        int cur = kti & 1;
        cpwait<0>(); __syncthreads();
        if (kti+1 < NKT){ issue_kv((kti+1)*64, cur^1); cpcommit(); }

        // S = Q @ K^T
        float sa[8][4];
        #pragma unroll
        for (int i = 0; i < 8; i++){ sa[i][0]=0.f; sa[i][1]=0.f; sa[i][2]=0.f; sa[i][3]=0.f; }
        #pragma unroll
        for (int ks = 0; ks < 4; ++ks){
            #pragma unroll
            for (int nf2 = 0; nf2 < 4; ++nf2){
                uint32_t r[4];
                ldsm4(r, sptr(&Ks[cur][(nf2*16 + (lane&15))*72 + ks*16 + (lane>>4)*8]));
                uint32_t blo[2] = {r[0], r[2]}, bhi[2] = {r[1], r[3]};
                mma16816(sa[nf2*2],   aQ[ks], blo);
                mma16816(sa[nf2*2+1], aQ[ks], bhi);
            }
        }
        // online softmax
        float cm0 = -1e30f, cm1 = -1e30f;
        #pragma unroll
        for (int nt = 0; nt < 8; ++nt){
            sa[nt][0]*=0.125f; sa[nt][1]*=0.125f; sa[nt][2]*=0.125f; sa[nt][3]*=0.125f;
            cm0 = fmaxf(cm0, fmaxf(sa[nt][0], sa[nt][1]));
            cm1 = fmaxf(cm1, fmaxf(sa[nt][2], sa[nt][3]));
        }
        cm0 = fmaxf(cm0, __shfl_xor_sync(0xffffffffu, cm0, 1));
        cm0 = fmaxf(cm0, __shfl_xor_sync(0xffffffffu, cm0, 2));
        cm1 = fmaxf(cm1, __shfl_xor_sync(0xffffffffu, cm1, 1));
        cm1 = fmaxf(cm1, __shfl_xor_sync(0xffffffffu, cm1, 2));
        float nm0 = fmaxf(m0, cm0), nm1 = fmaxf(m1, cm1);
        float a0 = __expf(m0 - nm0), a1 = __expf(m1 - nm1);
        float rs0 = 0.f, rs1 = 0.f;
        #pragma unroll
        for (int nt = 0; nt < 8; ++nt){
            sa[nt][0] = __expf(sa[nt][0] - nm0); rs0 += sa[nt][0];
            sa[nt][1] = __expf(sa[nt][1] - nm0); rs0 += sa[nt][1];
            sa[nt][2] = __expf(sa[nt][2] - nm1); rs1 += sa[nt][2];
            sa[nt][3] = __expf(sa[nt][3] - nm1); rs1 += sa[nt][3];
        }
        rs0 += __shfl_xor_sync(0xffffffffu, rs0, 1);
        rs0 += __shfl_xor_sync(0xffffffffu, rs0, 2);
        rs1 += __shfl_xor_sync(0xffffffffu, rs1, 1);
        rs1 += __shfl_xor_sync(0xffffffffu, rs1, 2);
        l0 = l0*a0 + rs0; l1 = l1*a1 + rs1; m0 = nm0; m1 = nm1;
        #pragma unroll
        for (int nt = 0; nt < 8; ++nt){ oa[nt][0]*=a0; oa[nt][1]*=a0; oa[nt][2]*=a1; oa[nt][3]*=a1; }
        // P -> half a-frags
        uint32_t pa[4][4];
        #pragma unroll
        for (int kf = 0; kf < 4; ++kf){
            pa[kf][0] = packh2(sa[2*kf][0],   sa[2*kf][1]);
            pa[kf][1] = packh2(sa[2*kf][2],   sa[2*kf][3]);
            pa[kf][2] = packh2(sa[2*kf+1][0], sa[2*kf+1][1]);
            pa[kf][3] = packh2(sa[2*kf+1][2], sa[2*kf+1][3]);
        }
        // O += P @ V
        #pragma unroll
        for (int kf = 0; kf < 4; ++kf){
            #pragma unroll
            for (int nf2 = 0; nf2 < 4; ++nf2){
                uint32_t r[4];
                ldsm4t(r, sptr(&Vs[cur][(kf*16 + (lane&15))*72 + nf2*16 + (lane>>4)*8]));
                uint32_t blo[2] = {r[0], r[1]}, bhi[2] = {r[2], r[3]};
                mma16816(oa[nf2*2],   pa[kf], blo);
                mma16816(oa[nf2*2+1], pa[kf], bhi);
            }
        }
    }

    float il0 = 1.f / l0, il1 = 1.f / l1;
    int rlo = q0 + w*16 + (lane>>2);
    #pragma unroll
    for (int nt = 0; nt < 8; ++nt){
        int c = h*64 + nt*8 + (lane&3)*2;
        *(__half2*)(o + ((long)b*S_ + rlo)*D_ + c)     = __floats2half2_rn(oa[nt][0]*il0, oa[nt][1]*il0);
        *(__half2*)(o + ((long)b*S_ + rlo + 8)*D_ + c) = __floats2half2_rn(oa[nt][2]*il1, oa[nt][3]*il1);
    }
}

// ---------------- MoE routing ----------------
__global__ __launch_bounds__(256) void moe_init_k(){
    int i = blockIdx.x*256 + threadIdx.x;
    if (i < MROWS) g_gather[i] = -1;
    if (i < E_){ g_counts[i] = 0; g_cursor[i] = 0; }
}

__global__ __launch_bounds__(256) void gate_k(const float* __restrict__ xf, const float* __restrict__ gw){
    int n = blockIdx.x;
    int tid = threadIdx.x, w = tid >> 5, lane = tid & 31;
    const float* xr = xf + (long)n * D_;
    const float* gr = gw + (long)w * D_;
    float s = 0.f;
    for (int d = lane; d < D_; d += 32) s += xr[d] * gr[d];
    #pragma unroll
    for (int o = 16; o; o >>= 1) s += __shfl_xor_sync(0xffffffffu, s, o);
    __shared__ float sc[E_];
    if (lane == 0) sc[w] = s;
    __syncthreads();
    if (tid == 0){
        float mx = sc[0];
        for (int e = 1; e < E_; e++) mx = fmaxf(mx, sc[e]);
        float p[E_]; float sum = 0.f;
        for (int e = 0; e < E_; e++){ p[e] = expf(sc[e] - mx); sum += p[e]; }
        float inv = 1.f / sum;
        for (int e = 0; e < E_; e++) p[e] *= inv;
        int e0 = 0;
        for (int e = 1; e < E_; e++) if (p[e] > p[e0]) e0 = e;
        int e1 = (e0 == 0) ? 1 : 0;
        for (int e = 0; e < E_; e++){ if (e == e0) continue; if (p[e] > p[e1]) e1 = e; }
        float v0 = p[e0], v1 = p[e1];
        float wi = 1.f / (v0 + v1 + 1e-9f);
        g_tokE[2*n] = e0; g_tokE[2*n+1] = e1;
        g_tokW[2*n] = v0*wi; g_tokW[2*n+1] = v1*wi;
        atomicAdd(&g_counts[e0], 1);
        atomicAdd(&g_counts[e1], 1);
    }
}

__global__ void offsets_k(){
    if (threadIdx.x == 0){
        int acc = 0;
        for (int e = 0; e < E_; e++){ g_padbase[e] = acc; acc += ((g_counts[e] + 127) >> 7) << 7; }
        g_padbase[E_] = acc;
    }
    __syncthreads();
    int t = threadIdx.x;
    if (t < NTILES){
        int start = t*128, te = 0;
        if (start < g_padbase[E_]){
            for (int e = 0; e < E_; e++)
                if (start >= g_padbase[e] && start < g_padbase[e+1]) te = e;
        }
        g_tileE[t] = te;
    }
}

__global__ __launch_bounds__(256) void scatter_k(){
    int n = blockIdx.x*256 + threadIdx.x;
    if (n >= NTOK) return;
    #pragma unroll
    for (int kk = 0; kk < 2; kk++){
        int e = g_tokE[2*n + kk];
        int slot = atomicAdd(&g_cursor[e], 1);
        int pos = g_padbase[e] + slot;
        g_gather[pos] = n;
        g_tokPos[2*n + kk] = pos;
    }
}

__global__ __launch_bounds__(256) void combine_k(float* __restrict__ out){
    int i = blockIdx.x*256 + threadIdx.x;
    int n = i >> 10, d = i & 1023;
    float v = g_h[i] + g_sh[i];
    v += g_tokW[2*n]   * g_eo[(long)g_tokPos[2*n]  * D_ + d];
    v += g_tokW[2*n+1] * g_eo[(long)g_tokPos[2*n+1]* D_ + d];
    out[i] = v;
}

// ---------------- host orchestration ----------------
extern "C" void kernel_launch(void* const* d_in, const int* in_sizes, int n_in,
                              void* d_out, int out_size) {
    const float* x   = (const float*)d_in[0];
    const float* fc  = (const float*)d_in[1];
    const float* fs  = (const float*)d_in[2];
    const float* anw = (const float*)d_in[3];
    const float* fnw = (const float*)d_in[4];
    const float* wq  = (const float*)d_in[5];
    const float* wk  = (const float*)d_in[6];
    const float* wv  = (const float*)d_in[7];
    const float* wo  = (const float*)d_in[8];
    const float* gw  = (const float*)d_in[9];
    const float* ew1 = (const float*)d_in[10];
    const float* ew2 = (const float*)d_in[11];
    const float* ew3 = (const float*)d_in[12];
    const float* sw1 = (const float*)d_in[13];
    const float* sw2 = (const float*)d_in[14];
    const float* sw3 = (const float*)d_in[15];
    float* out = (float*)d_out;

    float *qkv,*h,*xf,*s1,*sh,*m1,*eo;
    __half *xnh,*qh,*kh,*vh,*atth,*xfh,*th,*h1h;
    __half *wqkvh,*woh,*sw1h,*sw2h,*sw3h,*ew1h,*ew2h,*ew3h;
    int *gath,*tileE;
    cudaGetSymbolAddress((void**)&qkv, g_qkv);
    cudaGetSymbolAddress((void**)&h,   g_h);
    cudaGetSymbolAddress((void**)&xf,  g_xf);
    cudaGetSymbolAddress((void**)&s1,  g_s1);
    cudaGetSymbolAddress((void**)&sh,  g_sh);
    cudaGetSymbolAddress((void**)&m1,  g_m1);
    cudaGetSymbolAddress((void**)&eo,  g_eo);
    cudaGetSymbolAddress((void**)&xnh, g_xnh);
    cudaGetSymbolAddress((void**)&qh,  g_qh);
    cudaGetSymbolAddress((void**)&kh,  g_kh);
    cudaGetSymbolAddress((void**)&vh,  g_vh);
    cudaGetSymbolAddress((void**)&atth,g_atth);
    cudaGetSymbolAddress((void**)&xfh, g_xfh);
    cudaGetSymbolAddress((void**)&th,  g_th);
    cudaGetSymbolAddress((void**)&h1h, g_h1h);
    cudaGetSymbolAddress((void**)&wqkvh,g_wqkvh);
    cudaGetSymbolAddress((void**)&woh, g_woh);
    cudaGetSymbolAddress((void**)&sw1h,g_sw1h);
    cudaGetSymbolAddress((void**)&sw2h,g_sw2h);
    cudaGetSymbolAddress((void**)&sw3h,g_sw3h);
    cudaGetSymbolAddress((void**)&ew1h,g_ew1h);
    cudaGetSymbolAddress((void**)&ew2h,g_ew2h);
    cudaGetSymbolAddress((void**)&ew3h,g_ew3h);
    cudaGetSymbolAddress((void**)&gath,  g_gather);
    cudaGetSymbolAddress((void**)&tileE, g_tileE);

    const long estride = (long)D_ * D_;
    const int n1M4 = (D_*D_)/4, n8M4 = (E_*D_*D_)/4;

    // weight conversions (graph-static, ~25us)
    cvtqkv_k<<<(D_*D_)/256, 256>>>(wq, wk, wv, wqkvh);
    cvt4_k<<<n1M4/256, 256>>>((const float4*)wo,  (__half2*)woh,  n1M4);
    cvt4_k<<<n1M4/256, 256>>>((const float4*)sw1, (__half2*)sw1h, n1M4);
    cvt4_k<<<n1M4/256, 256>>>((const float4*)sw2, (__half2*)sw2h, n1M4);
    cvt4_k<<<n1M4/256, 256>>>((const float4*)sw3, (__half2*)sw3h, n1M4);
    cvt4_k<<<n8M4/256, 256>>>((const float4*)ew1, (__half2*)ew1h, n8M4);
    cvt4_k<<<n8M4/256, 256>>>((const float4*)ew2, (__half2*)ew2h, n8M4);
    cvt4_k<<<n8M4/256, 256>>>((const float4*)ew3, (__half2*)ew3h, n8M4);

    // attention path
    rmsnorm_k<<<NTOK, 256>>>(x, anw, nullptr, xnh);
    hgemm_k<float,0><<<dim3(24,32), 256>>>(xnh, wqkvh, qkv, nullptr, 1024, 3072, nullptr, nullptr, 0);
    rope_k<<<(NTOK*512)/256, 256>>>(qkv, qh, kh, vh, fc, fs);
    flash_h_k<<<dim3(S_/64, B_*H_), 128>>>(qh, kh, vh, atth);
    hgemm_k<float,1><<<dim3(8,32), 256>>>(atth, woh, h, x, 1024, 1024, nullptr, nullptr, 0);

    // FFN path
    rmsnorm_k<<<NTOK, 256>>>(h, fnw, xf, xfh);
    hgemm_k<float,0><<<dim3(8,32), 256>>>(xfh, sw1h, s1, nullptr, 1024, 1024, nullptr, nullptr, 0);
    hgemm_k<__half,2><<<dim3(8,32), 256>>>(xfh, sw3h, th, s1, 1024, 1024, nullptr, nullptr, 0);
    hgemm_k<float,0><<<dim3(8,32), 256>>>(th, sw2h, sh, nullptr, 1024, 1024, nullptr, nullptr, 0);

    // MoE routing
    moe_init_k<<<(MROWS + 255)/256, 256>>>();
    gate_k<<<NTOK, 256>>>(xf, gw);
    offsets_k<<<1, 128>>>();
    scatter_k<<<NTOK/256, 256>>>();

    // grouped expert GEMMs
    hgemm_k<float,0><<<dim3(8,NTILES), 256>>>(xfh, ew1h, m1, nullptr, 1024, 1024, gath, tileE, estride);
    hgemm_k<__half,2><<<dim3(8,NTILES), 256>>>(xfh, ew3h, h1h, m1, 1024, 1024, gath, tileE, estride);
    hgemm_k<float,0><<<dim3(8,NTILES), 256>>>(h1h, ew2h, eo, nullptr, 1024, 1024, nullptr, tileE, estride);

    combine_k<<<(NTOK*D_)/256, 256>>>(out);
}

// round 5
// speedup vs baseline: 5.3591x; 1.0181x over previous
#include <cuda_runtime.h>
#include <cuda_fp16.h>
#include <cstdint>
#include <math.h>

#define B_    2
#define S_    2048
#define D_    1024
#define H_    16
#define NTOK  4096
#define E_    8
#define MROWS 9216
#define NTILES 72
#define M1Q   262144   // D*D/4 float4s per 1M-element matrix

// ---------------- device scratch ----------------
__device__ float g_h  [NTOK*D_];
__device__ float g_xf [NTOK*D_];
__device__ float g_s1 [NTOK*D_];
__device__ float g_sh [NTOK*D_];
__device__ float g_m1 [MROWS*D_];
__device__ float g_eo [MROWS*D_];

__device__ __half g_qkvh[NTOK*3072];
__device__ __half g_xnh [NTOK*D_];
__device__ __half g_qh  [NTOK*D_];
__device__ __half g_kh  [NTOK*D_];
__device__ __half g_vh  [NTOK*D_];
__device__ __half g_atth[NTOK*D_];
__device__ __half g_xfh [NTOK*D_];
__device__ __half g_th  [NTOK*D_];
__device__ __half g_h1h [MROWS*D_];

__device__ __half g_wqkvh[D_*3072];
__device__ __half g_woh [D_*D_];
__device__ __half g_sw1h[D_*D_];
__device__ __half g_sw2h[D_*D_];
__device__ __half g_sw3h[D_*D_];
__device__ __half g_ew1h[E_*D_*D_];
__device__ __half g_ew2h[E_*D_*D_];
__device__ __half g_ew3h[E_*D_*D_];

__device__ int   g_counts [E_];
__device__ int   g_cursor [E_];
__device__ int   g_padbase[E_+1];
__device__ int   g_tileE  [NTILES];
__device__ int   g_gather [MROWS];
__device__ int   g_tokE   [NTOK*2];
__device__ float g_tokW   [NTOK*2];
__device__ int   g_tokPos [NTOK*2];

// ---------------- ptx helpers ----------------
__device__ __forceinline__ uint32_t sptr(const void* p){ return (uint32_t)__cvta_generic_to_shared(p); }
__device__ __forceinline__ void ldsm4(uint32_t* r, uint32_t a){
    asm volatile("ldmatrix.sync.aligned.m8n8.x4.shared.b16 {%0,%1,%2,%3},[%4];"
        :"=r"(r[0]),"=r"(r[1]),"=r"(r[2]),"=r"(r[3]):"r"(a));
}
__device__ __forceinline__ void ldsm4t(uint32_t* r, uint32_t a){
    asm volatile("ldmatrix.sync.aligned.m8n8.x4.trans.shared.b16 {%0,%1,%2,%3},[%4];"
        :"=r"(r[0]),"=r"(r[1]),"=r"(r[2]),"=r"(r[3]):"r"(a));
}
__device__ __forceinline__ void mma16816(float* c, const uint32_t* a, const uint32_t* b){
    asm volatile("mma.sync.aligned.m16n8k16.row.col.f32.f16.f16.f32 "
        "{%0,%1,%2,%3},{%4,%5,%6,%7},{%8,%9},{%0,%1,%2,%3};"
        :"+f"(c[0]),"+f"(c[1]),"+f"(c[2]),"+f"(c[3])
        :"r"(a[0]),"r"(a[1]),"r"(a[2]),"r"(a[3]),"r"(b[0]),"r"(b[1]));
}
__device__ __forceinline__ void cp16(uint32_t d, const void* s){
    asm volatile("cp.async.cg.shared.global [%0],[%1],16;"::"r"(d),"l"(s));
}
__device__ __forceinline__ void cpcommit(){ asm volatile("cp.async.commit_group;"); }
template<int N> __device__ __forceinline__ void cpwait(){ asm volatile("cp.async.wait_group %0;"::"n"(N)); }
__device__ __forceinline__ uint32_t packh2(float a, float b){
    __half2 h = __floats2half2_rn(a,b); return *(uint32_t*)&h;
}

// ---------------- single merged weight conversion ----------------
// regions (float4 units): [0,4*M1Q): wo,sw1,sw2,sw3 ; [4*M1Q,28*M1Q): ew1,ew2,ew3 ;
// [28*M1Q,31*M1Q): wq,wk,wv interleaved into wqkvh
__global__ __launch_bounds__(256) void cvtall_k(
    const float4* __restrict__ wq, const float4* __restrict__ wk, const float4* __restrict__ wv,
    const float4* __restrict__ wo, const float4* __restrict__ sw1,
    const float4* __restrict__ sw2, const float4* __restrict__ sw3,
    const float4* __restrict__ ew1, const float4* __restrict__ ew2, const float4* __restrict__ ew3)
{
    int i = blockIdx.x*256 + threadIdx.x;
    float4 v; __half* dst; long eo4;
    if (i < 4*M1Q){
        int m = i >> 18, t = i & (M1Q-1);
        const float4* s = (m==0)? wo : (m==1)? sw1 : (m==2)? sw2 : sw3;
        dst = (m==0)? g_woh : (m==1)? g_sw1h : (m==2)? g_sw2h : g_sw3h;
        v = s[t]; eo4 = (long)t*4;
    } else if (i < 28*M1Q){
        int j = i - 4*M1Q;
        int m = j / (8*M1Q);           // 0,1,2
        int t = j - m*8*M1Q;
        const float4* s = (m==0)? ew1 : (m==1)? ew2 : ew3;
        dst = (m==0)? g_ew1h : (m==1)? g_ew2h : g_ew3h;
        v = s[t]; eo4 = (long)t*4;
    } else {
        int j = i - 28*M1Q;
        int m = j >> 18, t = j & (M1Q-1);
        const float4* s = (m==0)? wq : (m==1)? wk : wv;
        v = s[t];
        long e = (long)t*4;
        long k = e >> 10, c = e & 1023;
        dst = g_wqkvh; eo4 = k*3072 + m*1024 + c;
    }
    __half2 h0 = __floats2half2_rn(v.x, v.y), h1 = __floats2half2_rn(v.z, v.w);
    uint2 packed; packed.x = *(uint32_t*)&h0; packed.y = *(uint32_t*)&h1;
    *(uint2*)(dst + eo4) = packed;
}

// ---------------- rmsnorm (fp32 in, optional fp32 + half out) ----------------
__global__ __launch_bounds__(256) void rmsnorm_k(const float* __restrict__ x, const float* __restrict__ w,
                                                 float* __restrict__ yf, __half* __restrict__ yh){
    int n = blockIdx.x;
    const float* xr = x + (long)n * D_;
    float v[4]; float ss = 0.f;
    #pragma unroll
    for (int u = 0; u < 4; u++){ v[u] = xr[threadIdx.x + u*256]; ss += v[u]*v[u]; }
    __shared__ float red[256];
    red[threadIdx.x] = ss; __syncthreads();
    for (int s = 128; s > 0; s >>= 1){
        if (threadIdx.x < s) red[threadIdx.x] += red[threadIdx.x + s];
        __syncthreads();
    }
    float r = rsqrtf(red[0] / (float)D_ + 1e-6f);
    #pragma unroll
    for (int u = 0; u < 4; u++){
        int c = threadIdx.x + u*256;
        float val = v[u]*r*w[c];
        yh[(long)n*D_ + c] = __float2half(val);
        if (yf) yf[(long)n*D_ + c] = val;
    }
}

// ---------------- RoPE: qkvh half -> qh,kh,vh half ----------------
__global__ __launch_bounds__(256) void rope_k(const __half* __restrict__ qkv,
                                              __half* __restrict__ qh, __half* __restrict__ kh, __half* __restrict__ vh,
                                              const float* __restrict__ fc, const float* __restrict__ fs){
    int i = blockIdx.x*256 + threadIdx.x;   // pair index, NTOK*512 total
    int n = i >> 9, p = i & 511;
    int c = p*2;
    int fi = (c & 63) >> 1;
    int s = n & (S_-1);
    float cc = fc[s*32 + fi], sn = fs[s*32 + fi];
    long gb = (long)n*3072 + c;
    long ob = (long)n*D_ + c;
    float2 qv = __half22float2(*(const __half2*)(qkv + gb));
    *(__half2*)(qh + ob) = __floats2half2_rn(qv.x*cc - qv.y*sn, qv.x*sn + qv.y*cc);
    float2 kv = __half22float2(*(const __half2*)(qkv + gb + 1024));
    *(__half2*)(kh + ob) = __floats2half2_rn(kv.x*cc - kv.y*sn, kv.x*sn + kv.y*cc);
    *(__half2*)(vh + ob) = *(const __half2*)(qkv + gb + 2048);
}

// ---------------- HGEMM 128x128x32 double-buffered, mma.sync ----------------
#define ASTR 40
#define BSTR 136
template<typename OutT, int EPI>
__global__ __launch_bounds__(256) void hgemm_k(
    const __half* __restrict__ A, const __half* __restrict__ Bw,
    OutT* __restrict__ C, const float* __restrict__ C2,
    int K, int N,
    const int* __restrict__ gatherIdx, const int* __restrict__ tileExpert, long estride)
{
    __shared__ __half As[2][128*ASTR];
    __shared__ __half Bs[2][32*BSTR];
    const int tid = threadIdx.x, lane = tid & 31, wid = tid >> 5;
    const int wm = wid & 1, wn = wid >> 1;
    const int row0 = blockIdx.y*128, col0 = blockIdx.x*128;
    const __half* Bp = Bw + (tileExpert ? (long)tileExpert[blockIdx.y]*estride : 0);

    const int ar = tid >> 1, ac = tid & 1;
    long arow = 0; bool azero = false;
    if (gatherIdx){ int g = gatherIdx[row0 + ar]; if (g < 0) azero = true; else arow = (long)g*K; }
    else arow = (long)(row0 + ar)*K;
    const int br = tid >> 4, bc = tid & 15;

    float acc[4][4][4];
    #pragma unroll
    for (int a=0;a<4;a++)
        #pragma unroll
        for (int b=0;b<4;b++)
            #pragma unroll
            for (int c=0;c<4;c++) acc[a][b][c]=0.f;

    const int NIT = K >> 5;
    auto issue = [&](int it, int buf){
        int k0 = it << 5;
        #pragma unroll
        for (int u = 0; u < 2; u++){
            int c = ac + u*2;
            if (azero) *(uint4*)(&As[buf][ar*ASTR + c*8]) = make_uint4(0,0,0,0);
            else cp16(sptr(&As[buf][ar*ASTR + c*8]), A + arow + k0 + c*8);
        }
        #pragma unroll
        for (int u = 0; u < 2; u++){
            int r = br + u*16;
            cp16(sptr(&Bs[buf][r*BSTR + bc*8]), Bp + (long)(k0 + r)*N + col0 + bc*8);
        }
    };

    issue(0,0); cpcommit();
    for (int it = 0; it < NIT; ++it){
        int cur = it & 1;
        cpwait<0>(); __syncthreads();
        if (it+1 < NIT){ issue(it+1, cur^1); cpcommit(); }
        #pragma unroll
        for (int ks = 0; ks < 2; ++ks){
            uint32_t af[4][4];
            #pragma unroll
            for (int mf = 0; mf < 4; ++mf)
                ldsm4(af[mf], sptr(&As[cur][(wm*64 + mf*16 + (lane&15))*ASTR + ks*16 + (lane>>4)*8]));
            uint32_t bf[4][2];
            #pragma unroll
            for (int nf2 = 0; nf2 < 2; ++nf2){
                uint32_t r[4];
                ldsm4t(r, sptr(&Bs[cur][(ks*16 + (lane&15))*BSTR + wn*32 + nf2*16 + (lane>>4)*8]));
                bf[nf2*2][0]=r[0]; bf[nf2*2][1]=r[1]; bf[nf2*2+1][0]=r[2]; bf[nf2*2+1][1]=r[3];
            }
            #pragma unroll
            for (int mf = 0; mf < 4; ++mf)
                #pragma unroll
                for (int nt = 0; nt < 4; ++nt)
                    mma16816(acc[mf][nt], af[mf], bf[nt]);
        }
    }

    #pragma unroll
    for (int mf = 0; mf < 4; ++mf){
        int r = row0 + wm*64 + mf*16 + (lane>>2);
        #pragma unroll
        for (int nt = 0; nt < 4; ++nt){
            int c = col0 + wn*32 + nt*8 + (lane&3)*2;
            #pragma unroll
            for (int hh = 0; hh < 2; ++hh){
                long i = (long)(r + hh*8)*N + c;
                float v0 = acc[mf][nt][hh*2], v1 = acc[mf][nt][hh*2+1];
                if (EPI == 1){ float2 rr = *(const float2*)(C2 + i); v0 += rr.x; v1 += rr.y; }
                else if (EPI == 2){
                    float2 ss = *(const float2*)(C2 + i);
                    v0 *= ss.x / (1.f + __expf(-ss.x));
                    v1 *= ss.y / (1.f + __expf(-ss.y));
                }
                if (sizeof(OutT) == 2) *(__half2*)((__half*)C + i) = __floats2half2_rn(v0, v1);
                else { float2 w2; w2.x = v0; w2.y = v1; *(float2*)((float*)C + i) = w2; }
            }
        }
    }
}

// ---------------- flash attention fp16 (FA2-style), 64 q-rows / block ----------------
__global__ __launch_bounds__(128) void flash_h_k(const __half* __restrict__ qh, const __half* __restrict__ kh,
                                                 const __half* __restrict__ vh, __half* __restrict__ o){
    __shared__ __half Qs[64*72];
    __shared__ __half Ks[2][64*72];
    __shared__ __half Vs[2][64*72];
    const int tid = threadIdx.x, lane = tid & 31, w = tid >> 5;
    const int bh = blockIdx.y, b = bh >> 4, h = bh & 15;
    const int q0 = blockIdx.x*64;
    const int lrow = tid >> 1, lc0 = (tid & 1)*4;

    {
        const __half* qb = qh + ((long)b*S_ + q0 + lrow)*D_ + h*64;
        #pragma unroll
        for (int c = 0; c < 4; c++)
            cp16(sptr(&Qs[lrow*72 + (lc0 + c)*8]), qb + (lc0 + c)*8);
        cpcommit();
    }
    auto issue_kv = [&](int kt, int buf){
        const __half* kb = kh + ((long)b*S_ + kt + lrow)*D_ + h*64;
        const __half* vb = vh + ((long)b*S_ + kt + lrow)*D_ + h*64;
        #pragma unroll
        for (int c = 0; c < 4; c++){
            cp16(sptr(&Ks[buf][lrow*72 + (lc0 + c)*8]), kb + (lc0 + c)*8);
            cp16(sptr(&Vs[buf][lrow*72 + (lc0 + c)*8]), vb + (lc0 + c)*8);
        }
    };
    issue_kv(0, 0); cpcommit();

    cpwait<1>(); __syncthreads();
    uint32_t aQ[4][4];
    #pragma unroll
    for (int ks = 0; ks < 4; ks++)
        ldsm4(aQ[ks], sptr(&Qs[(w*16 + (lane&15))*72 + ks*16 + (lane>>4)*8]));

    float oa[8][4];
    #pragma unroll
    for (int i = 0; i < 8; i++){ oa[i][0]=0.f; oa[i][1]=0.f; oa[i][2]=0.f; oa[i][3]=0.f; }
    float m0 = -1e30f, m1 = -1e30f, l0 = 0.f, l1 = 0.f;

    const int NKT = S_/64;
    for (int kti = 0; kti < NKT; ++kti){
        int cur = kti & 1;
        cpwait<0>(); __syncthreads();
        if (kti+1 < NKT){ issue_kv((kti+1)*64, cur^1); cpcommit(); }

        float sa[8][4];
        #pragma unroll
        for (int i = 0; i < 8; i++){ sa[i][0]=0.f; sa[i][1]=0.f; sa[i][2]=0.f; sa[i][3]=0.f; }
        #pragma unroll
        for (int ks = 0; ks < 4; ++ks){
            #pragma unroll
            for (int nf2 = 0; nf2 < 4; ++nf2){
                uint32_t r[4];
                ldsm4(r, sptr(&Ks[cur][(nf2*16 + (lane&15))*72 + ks*16 + (lane>>4)*8]));
                uint32_t blo[2] = {r[0], r[2]}, bhi[2] = {r[1], r[3]};
                mma16816(sa[nf2*2],   aQ[ks], blo);
                mma16816(sa[nf2*2+1], aQ[ks], bhi);
            }
        }
        float cm0 = -1e30f, cm1 = -1e30f;
        #pragma unroll
        for (int nt = 0; nt < 8; ++nt){
            sa[nt][0]*=0.125f; sa[nt][1]*=0.125f; sa[nt][2]*=0.125f; sa[nt][3]*=0.125f;
            cm0 = fmaxf(cm0, fmaxf(sa[nt][0], sa[nt][1]));
            cm1 = fmaxf(cm1, fmaxf(sa[nt][2], sa[nt][3]));
        }
        cm0 = fmaxf(cm0, __shfl_xor_sync(0xffffffffu, cm0, 1));
        cm0 = fmaxf(cm0, __shfl_xor_sync(0xffffffffu, cm0, 2));
        cm1 = fmaxf(cm1, __shfl_xor_sync(0xffffffffu, cm1, 1));
        cm1 = fmaxf(cm1, __shfl_xor_sync(0xffffffffu, cm1, 2));
        float nm0 = fmaxf(m0, cm0), nm1 = fmaxf(m1, cm1);
        float a0 = __expf(m0 - nm0), a1 = __expf(m1 - nm1);
        float rs0 = 0.f, rs1 = 0.f;
        #pragma unroll
        for (int nt = 0; nt < 8; ++nt){
            sa[nt][0] = __expf(sa[nt][0] - nm0); rs0 += sa[nt][0];
            sa[nt][1] = __expf(sa[nt][1] - nm0); rs0 += sa[nt][1];
            sa[nt][2] = __expf(sa[nt][2] - nm1); rs1 += sa[nt][2];
            sa[nt][3] = __expf(sa[nt][3] - nm1); rs1 += sa[nt][3];
        }
        rs0 += __shfl_xor_sync(0xffffffffu, rs0, 1);
        rs0 += __shfl_xor_sync(0xffffffffu, rs0, 2);
        rs1 += __shfl_xor_sync(0xffffffffu, rs1, 1);
        rs1 += __shfl_xor_sync(0xffffffffu, rs1, 2);
        l0 = l0*a0 + rs0; l1 = l1*a1 + rs1; m0 = nm0; m1 = nm1;
        #pragma unroll
        for (int nt = 0; nt < 8; ++nt){ oa[nt][0]*=a0; oa[nt][1]*=a0; oa[nt][2]*=a1; oa[nt][3]*=a1; }
        uint32_t pa[4][4];
        #pragma unroll
        for (int kf = 0; kf < 4; ++kf){
            pa[kf][0] = packh2(sa[2*kf][0],   sa[2*kf][1]);
            pa[kf][1] = packh2(sa[2*kf][2],   sa[2*kf][3]);
            pa[kf][2] = packh2(sa[2*kf+1][0], sa[2*kf+1][1]);
            pa[kf][3] = packh2(sa[2*kf+1][2], sa[2*kf+1][3]);
        }
        #pragma unroll
        for (int kf = 0; kf < 4; ++kf){
            #pragma unroll
            for (int nf2 = 0; nf2 < 4; ++nf2){
                uint32_t r[4];
                ldsm4t(r, sptr(&Vs[cur][(kf*16 + (lane&15))*72 + nf2*16 + (lane>>4)*8]));
                uint32_t blo[2] = {r[0], r[1]}, bhi[2] = {r[2], r[3]};
                mma16816(oa[nf2*2],   pa[kf], blo);
                mma16816(oa[nf2*2+1], pa[kf], bhi);
            }
        }
    }

    float il0 = 1.f / l0, il1 = 1.f / l1;
    int rlo = q0 + w*16 + (lane>>2);
    #pragma unroll
    for (int nt = 0; nt < 8; ++nt){
        int c = h*64 + nt*8 + (lane&3)*2;
        *(__half2*)(o + ((long)b*S_ + rlo)*D_ + c)     = __floats2half2_rn(oa[nt][0]*il0, oa[nt][1]*il0);
        *(__half2*)(o + ((long)b*S_ + rlo + 8)*D_ + c) = __floats2half2_rn(oa[nt][2]*il1, oa[nt][3]*il1);
    }
}

// ---------------- MoE routing ----------------
__global__ __launch_bounds__(256) void moe_init_k(){
    int i = blockIdx.x*256 + threadIdx.x;
    if (i < MROWS) g_gather[i] = -1;
    if (i < E_){ g_counts[i] = 0; g_cursor[i] = 0; }
}

__global__ __launch_bounds__(256) void gate_k(const float* __restrict__ xf, const float* __restrict__ gw){
    int n = blockIdx.x;
    int tid = threadIdx.x, w = tid >> 5, lane = tid & 31;
    const float* xr = xf + (long)n * D_;
    const float* gr = gw + (long)w * D_;
    float s = 0.f;
    for (int d = lane; d < D_; d += 32) s += xr[d] * gr[d];
    #pragma unroll
    for (int o = 16; o; o >>= 1) s += __shfl_xor_sync(0xffffffffu, s, o);
    __shared__ float sc[E_];
    if (lane == 0) sc[w] = s;
    __syncthreads();
    if (tid == 0){
        float mx = sc[0];
        for (int e = 1; e < E_; e++) mx = fmaxf(mx, sc[e]);
        float p[E_]; float sum = 0.f;
        for (int e = 0; e < E_; e++){ p[e] = expf(sc[e] - mx); sum += p[e]; }
        float inv = 1.f / sum;
        for (int e = 0; e < E_; e++) p[e] *= inv;
        int e0 = 0;
        for (int e = 1; e < E_; e++) if (p[e] > p[e0]) e0 = e;
        int e1 = (e0 == 0) ? 1 : 0;
        for (int e = 0; e < E_; e++){ if (e == e0) continue; if (p[e] > p[e1]) e1 = e; }
        float v0 = p[e0], v1 = p[e1];
        float wi = 1.f / (v0 + v1 + 1e-9f);
        g_tokE[2*n] = e0; g_tokE[2*n+1] = e1;
        g_tokW[2*n] = v0*wi; g_tokW[2*n+1] = v1*wi;
        atomicAdd(&g_counts[e0], 1);
        atomicAdd(&g_counts[e1], 1);
    }
}

__global__ void offsets_k(){
    if (threadIdx.x == 0){
        int acc = 0;
        for (int e = 0; e < E_; e++){ g_padbase[e] = acc; acc += ((g_counts[e] + 127) >> 7) << 7; }
        g_padbase[E_] = acc;
    }
    __syncthreads();
    int t = threadIdx.x;
    if (t < NTILES){
        int start = t*128, te = 0;
        if (start < g_padbase[E_]){
            for (int e = 0; e < E_; e++)
                if (start >= g_padbase[e] && start < g_padbase[e+1]) te = e;
        }
        g_tileE[t] = te;
    }
}

__global__ __launch_bounds__(256) void scatter_k(){
    int n = blockIdx.x*256 + threadIdx.x;
    if (n >= NTOK) return;
    #pragma unroll
    for (int kk = 0; kk < 2; kk++){
        int e = g_tokE[2*n + kk];
        int slot = atomicAdd(&g_cursor[e], 1);
        int pos = g_padbase[e] + slot;
        g_gather[pos] = n;
        g_tokPos[2*n + kk] = pos;
    }
}

__global__ __launch_bounds__(256) void combine_k(float* __restrict__ out){
    int i = blockIdx.x*256 + threadIdx.x;
    int n = i >> 10, d = i & 1023;
    float v = g_h[i] + g_sh[i];
    v += g_tokW[2*n]   * g_eo[(long)g_tokPos[2*n]  * D_ + d];
    v += g_tokW[2*n+1] * g_eo[(long)g_tokPos[2*n+1]* D_ + d];
    out[i] = v;
}

// ---------------- host orchestration ----------------
extern "C" void kernel_launch(void* const* d_in, const int* in_sizes, int n_in,
                              void* d_out, int out_size) {
    const float* x   = (const float*)d_in[0];
    const float* fc  = (const float*)d_in[1];
    const float* fs  = (const float*)d_in[2];
    const float* anw = (const float*)d_in[3];
    const float* fnw = (const float*)d_in[4];
    const float* wq  = (const float*)d_in[5];
    const float* wk  = (const float*)d_in[6];
    const float* wv  = (const float*)d_in[7];
    const float* wo  = (const float*)d_in[8];
    const float* gw  = (const float*)d_in[9];
    const float* ew1 = (const float*)d_in[10];
    const float* ew2 = (const float*)d_in[11];
    const float* ew3 = (const float*)d_in[12];
    const float* sw1 = (const float*)d_in[13];
    const float* sw2 = (const float*)d_in[14];
    const float* sw3 = (const float*)d_in[15];
    float* out = (float*)d_out;

    float *h,*xf,*s1,*sh,*m1,*eo;
    __half *qkvh,*xnh,*qh,*kh,*vh,*atth,*xfh,*th,*h1h;
    __half *wqkvh,*woh,*sw1h,*sw2h,*sw3h,*ew1h,*ew2h,*ew3h;
    int *gath,*tileE;
    cudaGetSymbolAddress((void**)&h,   g_h);
    cudaGetSymbolAddress((void**)&xf,  g_xf);
    cudaGetSymbolAddress((void**)&s1,  g_s1);
    cudaGetSymbolAddress((void**)&sh,  g_sh);
    cudaGetSymbolAddress((void**)&m1,  g_m1);
    cudaGetSymbolAddress((void**)&eo,  g_eo);
    cudaGetSymbolAddress((void**)&qkvh,g_qkvh);
    cudaGetSymbolAddress((void**)&xnh, g_xnh);
    cudaGetSymbolAddress((void**)&qh,  g_qh);
    cudaGetSymbolAddress((void**)&kh,  g_kh);
    cudaGetSymbolAddress((void**)&vh,  g_vh);
    cudaGetSymbolAddress((void**)&atth,g_atth);
    cudaGetSymbolAddress((void**)&xfh, g_xfh);
    cudaGetSymbolAddress((void**)&th,  g_th);
    cudaGetSymbolAddress((void**)&h1h, g_h1h);
    cudaGetSymbolAddress((void**)&wqkvh,g_wqkvh);
    cudaGetSymbolAddress((void**)&woh, g_woh);
    cudaGetSymbolAddress((void**)&sw1h,g_sw1h);
    cudaGetSymbolAddress((void**)&sw2h,g_sw2h);
    cudaGetSymbolAddress((void**)&sw3h,g_sw3h);
    cudaGetSymbolAddress((void**)&ew1h,g_ew1h);
    cudaGetSymbolAddress((void**)&ew2h,g_ew2h);
    cudaGetSymbolAddress((void**)&ew3h,g_ew3h);
    cudaGetSymbolAddress((void**)&gath,  g_gather);
    cudaGetSymbolAddress((void**)&tileE, g_tileE);

    const long estride = (long)D_ * D_;

    // launch 0: one merged weight conversion (31*M1Q float4s)
    cvtall_k<<<(31*M1Q)/256, 256>>>(
        (const float4*)wq, (const float4*)wk, (const float4*)wv,
        (const float4*)wo, (const float4*)sw1, (const float4*)sw2, (const float4*)sw3,
        (const float4*)ew1, (const float4*)ew2, (const float4*)ew3);

    // attention path (launches 1..6)
    rmsnorm_k<<<NTOK, 256>>>(x, anw, nullptr, xnh);
    hgemm_k<__half,0><<<dim3(24,32), 256>>>(xnh, wqkvh, qkvh, nullptr, 1024, 3072, nullptr, nullptr, 0);
    rope_k<<<(NTOK*512)/256, 256>>>(qkvh, qh, kh, vh, fc, fs);
    flash_h_k<<<dim3(S_/64, B_*H_), 128>>>(qh, kh, vh, atth);
    hgemm_k<float,1><<<dim3(8,32), 256>>>(atth, woh, h, x, 1024, 1024, nullptr, nullptr, 0);

    // FFN path
    rmsnorm_k<<<NTOK, 256>>>(h, fnw, xf, xfh);
    hgemm_k<float,0><<<dim3(8,32), 256>>>(xfh, sw1h, s1, nullptr, 1024, 1024, nullptr, nullptr, 0);
    hgemm_k<__half,2><<<dim3(8,32), 256>>>(xfh, sw3h, th, s1, 1024, 1024, nullptr, nullptr, 0);
    hgemm_k<float,0><<<dim3(8,32), 256>>>(th, sw2h, sh, nullptr, 1024, 1024, nullptr, nullptr, 0);

    // MoE routing
    moe_init_k<<<(MROWS + 255)/256, 256>>>();
    gate_k<<<NTOK, 256>>>(xf, gw);
    offsets_k<<<1, 128>>>();
    scatter_k<<<NTOK/256, 256>>>();

    // grouped expert GEMMs
    hgemm_k<float,0><<<dim3(8,NTILES), 256>>>(xfh, ew1h, m1, nullptr, 1024, 1024, gath, tileE, estride);
    hgemm_k<__half,2><<<dim3(8,NTILES), 256>>>(xfh, ew3h, h1h, m1, 1024, 1024, gath, tileE, estride);
    hgemm_k<float,0><<<dim3(8,NTILES), 256>>>(h1h, ew2h, eo, nullptr, 1024, 1024, nullptr, tileE, estride);

    combine_k<<<(NTOK*D_)/256, 256>>>(out);
}

// round 7
// speedup vs baseline: 5.5524x; 1.0361x over previous
#include <cuda_runtime.h>
#include <cuda_fp16.h>
#include <cstdint>
#include <math.h>

#define B_    2
#define S_    2048
#define D_    1024
#define H_    16
#define NTOK  4096
#define E_    8
#define MROWS 9216
#define NTILES 72
#define M1Q   262144   // (1024*1024)/4 float4s per 1M-element matrix

#define ASTR 40
#define BSTR 136
#define GEMM_SMEM (3*(128*ASTR + 32*BSTR)*2)   // 56832 bytes

// ---------------- device scratch ----------------
__device__ float g_h  [NTOK*D_];
__device__ float g_xf [NTOK*D_];
__device__ float g_sh [NTOK*D_];
__device__ float g_eo [MROWS*D_];

__device__ __half g_qkvs[3*NTOK*D_];   // q | k | v (post-rope)
__device__ __half g_xnh [NTOK*D_];
__device__ __half g_atth[NTOK*D_];
__device__ __half g_xfh [NTOK*D_];
__device__ __half g_th  [NTOK*D_];
__device__ __half g_h1h [MROWS*D_];

__device__ __half g_wqkvh[D_*3072];
__device__ __half g_woh  [D_*D_];
__device__ __half g_w13h [D_*2048];        // interleaved sw1/sw3
__device__ __half g_sw2h [D_*D_];
__device__ __half g_ew13h[E_*D_*2048];     // interleaved ew1/ew3 per expert
__device__ __half g_ew2h [E_*D_*D_];

__device__ int   g_counts [E_];
__device__ int   g_cursor [E_];
__device__ int   g_padbase[E_+1];
__device__ int   g_tileE  [NTILES];
__device__ int   g_gather [MROWS];
__device__ int   g_tokE   [NTOK*2];
__device__ float g_tokW   [NTOK*2];
__device__ int   g_tokPos [NTOK*2];

// ---------------- ptx helpers ----------------
__device__ __forceinline__ uint32_t sptr(const void* p){ return (uint32_t)__cvta_generic_to_shared(p); }
__device__ __forceinline__ void ldsm4(uint32_t* r, uint32_t a){
    asm volatile("ldmatrix.sync.aligned.m8n8.x4.shared.b16 {%0,%1,%2,%3},[%4];"
        :"=r"(r[0]),"=r"(r[1]),"=r"(r[2]),"=r"(r[3]):"r"(a));
}
__device__ __forceinline__ void ldsm4t(uint32_t* r, uint32_t a){
    asm volatile("ldmatrix.sync.aligned.m8n8.x4.trans.shared.b16 {%0,%1,%2,%3},[%4];"
        :"=r"(r[0]),"=r"(r[1]),"=r"(r[2]),"=r"(r[3]):"r"(a));
}
__device__ __forceinline__ void mma16816(float* c, const uint32_t* a, const uint32_t* b){
    asm volatile("mma.sync.aligned.m16n8k16.row.col.f32.f16.f16.f32 "
        "{%0,%1,%2,%3},{%4,%5,%6,%7},{%8,%9},{%0,%1,%2,%3};"
        :"+f"(c[0]),"+f"(c[1]),"+f"(c[2]),"+f"(c[3])
        :"r"(a[0]),"r"(a[1]),"r"(a[2]),"r"(a[3]),"r"(b[0]),"r"(b[1]));
}
__device__ __forceinline__ void cp16(uint32_t d, const void* s){
    asm volatile("cp.async.cg.shared.global [%0],[%1],16;"::"r"(d),"l"(s));
}
__device__ __forceinline__ void cpcommit(){ asm volatile("cp.async.commit_group;"); }
template<int N> __device__ __forceinline__ void cpwait(){ asm volatile("cp.async.wait_group %0;"::"n"(N)); }
__device__ __forceinline__ uint32_t packh2(float a, float b){
    __half2 h = __floats2half2_rn(a,b); return *(uint32_t*)&h;
}

// ---------------- merged weight conversion (fp32 -> fp16, with layout fusion) ----
__global__ __launch_bounds__(256) void cvtall_k(
    const float4* __restrict__ wq, const float4* __restrict__ wk, const float4* __restrict__ wv,
    const float4* __restrict__ wo, const float4* __restrict__ sw1,
    const float4* __restrict__ sw2, const float4* __restrict__ sw3,
    const float4* __restrict__ ew1, const float4* __restrict__ ew2, const float4* __restrict__ ew3)
{
    int i = blockIdx.x*256 + threadIdx.x;
    if (i < M1Q){
        float4 v = wo[i];
        uint2 p; p.x = packh2(v.x,v.y); p.y = packh2(v.z,v.w);
        *(uint2*)(g_woh + (long)i*4) = p;
    } else if (i < 2*M1Q){
        int t = i - M1Q;
        float4 v = sw2[t];
        uint2 p; p.x = packh2(v.x,v.y); p.y = packh2(v.z,v.w);
        *(uint2*)(g_sw2h + (long)t*4) = p;
    } else if (i < 3*M1Q){
        int t = i - 2*M1Q;
        long e4 = (long)t*4;
        float4 a = sw1[t], b = sw3[t];
        uint4 p; p.x = packh2(a.x,b.x); p.y = packh2(a.y,b.y);
        p.z = packh2(a.z,b.z); p.w = packh2(a.w,b.w);
        *(uint4*)(g_w13h + (e4>>10)*2048 + 2*(e4&1023)) = p;
    } else if (i < 11*M1Q){
        int t = i - 3*M1Q;
        float4 v = ew2[t];
        uint2 p; p.x = packh2(v.x,v.y); p.y = packh2(v.z,v.w);
        *(uint2*)(g_ew2h + (long)t*4) = p;
    } else if (i < 19*M1Q){
        int t = i - 11*M1Q;
        long e4 = (long)t*4;
        long ex = e4 >> 20;
        long rem = e4 & 1048575;
        float4 a = ew1[t], b = ew3[t];
        uint4 p; p.x = packh2(a.x,b.x); p.y = packh2(a.y,b.y);
        p.z = packh2(a.z,b.z); p.w = packh2(a.w,b.w);
        *(uint4*)(g_ew13h + ex*(1024l*2048) + (rem>>10)*2048 + 2*(rem&1023)) = p;
    } else {
        int j = i - 19*M1Q;
        int m = j >> 18, t = j & (M1Q-1);
        const float4* s = (m==0)? wq : (m==1)? wk : wv;
        float4 v = s[t];
        long e = (long)t*4;
        uint2 p; p.x = packh2(v.x,v.y); p.y = packh2(v.z,v.w);
        *(uint2*)(g_wqkvh + (e>>10)*3072 + m*1024 + (e&1023)) = p;
    }
}

// ---------------- rmsnorm (fp32 in, optional fp32 + half out) ----------------
__global__ __launch_bounds__(256) void rmsnorm_k(const float* __restrict__ x, const float* __restrict__ w,
                                                 float* __restrict__ yf, __half* __restrict__ yh){
    int n = blockIdx.x;
    const float* xr = x + (long)n * D_;
    float v[4]; float ss = 0.f;
    #pragma unroll
    for (int u = 0; u < 4; u++){ v[u] = xr[threadIdx.x + u*256]; ss += v[u]*v[u]; }
    __shared__ float red[256];
    red[threadIdx.x] = ss; __syncthreads();
    for (int s = 128; s > 0; s >>= 1){
        if (threadIdx.x < s) red[threadIdx.x] += red[threadIdx.x + s];
        __syncthreads();
    }
    float r = rsqrtf(red[0] / (float)D_ + 1e-6f);
    #pragma unroll
    for (int u = 0; u < 4; u++){
        int c = threadIdx.x + u*256;
        float val = v[u]*r*w[c];
        yh[(long)n*D_ + c] = __float2half(val);
        if (yf) yf[(long)n*D_ + c] = val;
    }
}

// ---------------- HGEMM 128x128x32, 3-stage cp.async pipeline, mma.sync ------
// EPI: 0 C=acc(f32) ; 1 C=acc+C2 (f32) ; 3 fused silu-mul (half, N/2 wide) ;
//      4 fused rope qkv epilogue
template<typename OutT, int EPI>
__global__ __launch_bounds__(256) void hgemm_k(
    const __half* __restrict__ A, const __half* __restrict__ Bw,
    OutT* __restrict__ C, const float* __restrict__ C2,
    int K, int N,
    const int* __restrict__ gatherIdx, const int* __restrict__ tileExpert, long estride,
    const float* __restrict__ fcp, const float* __restrict__ fsp)
{
    extern __shared__ __half smem[];
    __half* As = smem;                    // 3 stages of 128*ASTR
    __half* Bs = smem + 3*128*ASTR;       // 3 stages of 32*BSTR
    const int tid = threadIdx.x, lane = tid & 31, wid = tid >> 5;
    const int wm = wid & 1, wn = wid >> 1;
    const int row0 = blockIdx.y*128, col0 = blockIdx.x*128;
    const __half* Bp = Bw + (tileExpert ? (long)tileExpert[blockIdx.y]*estride : 0);

    const int ar = tid >> 1, ac = tid & 1;
    long arow = 0; bool azero = false;
    if (gatherIdx){ int g = gatherIdx[row0 + ar]; if (g < 0) azero = true; else arow = (long)g*K; }
    else arow = (long)(row0 + ar)*K;
    const int br = tid >> 4, bc = tid & 15;

    float acc[4][4][4];
    #pragma unroll
    for (int a=0;a<4;a++)
        #pragma unroll
        for (int b=0;b<4;b++)
            #pragma unroll
            for (int c=0;c<4;c++) acc[a][b][c]=0.f;

    const int NIT = K >> 5;
    auto issue = [&](int it, int buf){
        int k0 = it << 5;
        __half* Ab = As + buf*128*ASTR;
        __half* Bb = Bs + buf*32*BSTR;
        #pragma unroll
        for (int u = 0; u < 2; u++){
            int c = ac + u*2;
            if (azero) *(uint4*)(&Ab[ar*ASTR + c*8]) = make_uint4(0,0,0,0);
            else cp16(sptr(&Ab[ar*ASTR + c*8]), A + arow + k0 + c*8);
        }
        #pragma unroll
        for (int u = 0; u < 2; u++){
            int r = br + u*16;
            cp16(sptr(&Bb[r*BSTR + bc*8]), Bp + (long)(k0 + r)*N + col0 + bc*8);
        }
    };

    issue(0,0); cpcommit();
    issue(1,1); cpcommit();
    int cur = 0;
    for (int it = 0; it < NIT; ++it){
        cpwait<1>(); __syncthreads();
        if (it+2 < NIT){ issue(it+2, (it+2)%3); cpcommit(); }
        __half* Ab = As + cur*128*ASTR;
        __half* Bb = Bs + cur*32*BSTR;
        #pragma unroll
        for (int ks = 0; ks < 2; ++ks){
            uint32_t af[4][4];
            #pragma unroll
            for (int mf = 0; mf < 4; ++mf)
                ldsm4(af[mf], sptr(&Ab[(wm*64 + mf*16 + (lane&15))*ASTR + ks*16 + (lane>>4)*8]));
            uint32_t bf[4][2];
            #pragma unroll
            for (int nf2 = 0; nf2 < 2; ++nf2){
                uint32_t r[4];
                ldsm4t(r, sptr(&Bb[(ks*16 + (lane&15))*BSTR + wn*32 + nf2*16 + (lane>>4)*8]));
                bf[nf2*2][0]=r[0]; bf[nf2*2][1]=r[1]; bf[nf2*2+1][0]=r[2]; bf[nf2*2+1][1]=r[3];
            }
            #pragma unroll
            for (int mf = 0; mf < 4; ++mf)
                #pragma unroll
                for (int nt = 0; nt < 4; ++nt)
                    mma16816(acc[mf][nt], af[mf], bf[nt]);
        }
        cur = (cur+1)%3;
        __syncthreads();
    }

    #pragma unroll
    for (int mf = 0; mf < 4; ++mf){
        int rbase = row0 + wm*64 + mf*16 + (lane>>2);
        #pragma unroll
        for (int nt = 0; nt < 4; ++nt){
            int c = col0 + wn*32 + nt*8 + (lane&3)*2;
            #pragma unroll
            for (int hh = 0; hh < 2; ++hh){
                int rr = rbase + hh*8;
                float v0 = acc[mf][nt][hh*2], v1 = acc[mf][nt][hh*2+1];
                if (EPI == 0){
                    float2 w2; w2.x = v0; w2.y = v1;
                    *(float2*)((float*)C + (long)rr*N + c) = w2;
                } else if (EPI == 1){
                    float2 rr2 = *(const float2*)(C2 + (long)rr*N + c);
                    float2 w2; w2.x = v0 + rr2.x; w2.y = v1 + rr2.y;
                    *(float2*)((float*)C + (long)rr*N + c) = w2;
                } else if (EPI == 3){
                    float sv = v0 / (1.f + __expf(-v0)) * v1;
                    ((__half*)C)[(long)rr*(N>>1) + (c>>1)] = __float2half(sv);
                } else { // EPI == 4: rope + split to q|k|v
                    __half* base = (__half*)C;
                    int cc_ = c;
                    if (c >= 2048){ base += 2l*NTOK*D_; cc_ = c - 2048; }
                    else if (c >= 1024){ base += (long)NTOK*D_; cc_ = c - 1024; }
                    if (c < 2048){
                        int s = rr & (S_-1);
                        int fi = (cc_ & 63) >> 1;
                        float co = fcp[s*32+fi], sn = fsp[s*32+fi];
                        *(__half2*)(base + (long)rr*D_ + cc_) =
                            __floats2half2_rn(v0*co - v1*sn, v0*sn + v1*co);
                    } else {
                        *(__half2*)(base + (long)rr*D_ + cc_) = __floats2half2_rn(v0, v1);
                    }
                }
            }
        }
    }
}

// ---------------- flash attention fp16 (FA2-style), 64 q-rows / block --------
__global__ __launch_bounds__(128) void flash_h_k(const __half* __restrict__ qh, const __half* __restrict__ kh,
                                                 const __half* __restrict__ vh, __half* __restrict__ o){
    __shared__ __half Qs[64*72];
    __shared__ __half Ks[2][64*72];
    __shared__ __half Vs[2][64*72];
    const int tid = threadIdx.x, lane = tid & 31, w = tid >> 5;
    const int bh = blockIdx.y, b = bh >> 4, h = bh & 15;
    const int q0 = blockIdx.x*64;
    const int lrow = tid >> 1, lc0 = (tid & 1)*4;

    {
        const __half* qb = qh + ((long)b*S_ + q0 + lrow)*D_ + h*64;
        #pragma unroll
        for (int c = 0; c < 4; c++)
            cp16(sptr(&Qs[lrow*72 + (lc0 + c)*8]), qb + (lc0 + c)*8);
        cpcommit();
    }
    auto issue_kv = [&](int kt, int buf){
        const __half* kb = kh + ((long)b*S_ + kt + lrow)*D_ + h*64;
        const __half* vb = vh + ((long)b*S_ + kt + lrow)*D_ + h*64;
        #pragma unroll
        for (int c = 0; c < 4; c++){
            cp16(sptr(&Ks[buf][lrow*72 + (lc0 + c)*8]), kb + (lc0 + c)*8);
            cp16(sptr(&Vs[buf][lrow*72 + (lc0 + c)*8]), vb + (lc0 + c)*8);
        }
    };
    issue_kv(0, 0); cpcommit();

    cpwait<1>(); __syncthreads();
    uint32_t aQ[4][4];
    #pragma unroll
    for (int ks = 0; ks < 4; ks++)
        ldsm4(aQ[ks], sptr(&Qs[(w*16 + (lane&15))*72 + ks*16 + (lane>>4)*8]));

    float oa[8][4];
    #pragma unroll
    for (int i = 0; i < 8; i++){ oa[i][0]=0.f; oa[i][1]=0.f; oa[i][2]=0.f; oa[i][3]=0.f; }
    float m0 = -1e30f, m1 = -1e30f, l0 = 0.f, l1 = 0.f;

    const int NKT = S_/64;
    for (int kti = 0; kti < NKT; ++kti){
        int cur = kti & 1;
        cpwait<0>(); __syncthreads();
        if (kti+1 < NKT){ issue_kv((kti+1)*64, cur^1); cpcommit(); }

        float sa[8][4];
        #pragma unroll
        for (int i = 0; i < 8; i++){ sa[i][0]=0.f; sa[i][1]=0.f; sa[i][2]=0.f; sa[i][3]=0.f; }
        #pragma unroll
        for (int ks = 0; ks < 4; ++ks){
            #pragma unroll
            for (int nf2 = 0; nf2 < 4; ++nf2){
                uint32_t r[4];
                ldsm4(r, sptr(&Ks[cur][(nf2*16 + (lane&15))*72 + ks*16 + (lane>>4)*8]));
                uint32_t blo[2] = {r[0], r[2]}, bhi[2] = {r[1], r[3]};
                mma16816(sa[nf2*2],   aQ[ks], blo);
                mma16816(sa[nf2*2+1], aQ[ks], bhi);
            }
        }
        float cm0 = -1e30f, cm1 = -1e30f;
        #pragma unroll
        for (int nt = 0; nt < 8; ++nt){
            sa[nt][0]*=0.125f; sa[nt][1]*=0.125f; sa[nt][2]*=0.125f; sa[nt][3]*=0.125f;
            cm0 = fmaxf(cm0, fmaxf(sa[nt][0], sa[nt][1]));
            cm1 = fmaxf(cm1, fmaxf(sa[nt][2], sa[nt][3]));
        }
        cm0 = fmaxf(cm0, __shfl_xor_sync(0xffffffffu, cm0, 1));
        cm0 = fmaxf(cm0, __shfl_xor_sync(0xffffffffu, cm0, 2));
        cm1 = fmaxf(cm1, __shfl_xor_sync(0xffffffffu, cm1, 1));
        cm1 = fmaxf(cm1, __shfl_xor_sync(0xffffffffu, cm1, 2));
        float nm0 = fmaxf(m0, cm0), nm1 = fmaxf(m1, cm1);
        float a0 = __expf(m0 - nm0), a1 = __expf(m1 - nm1);
        float rs0 = 0.f, rs1 = 0.f;
        #pragma unroll
        for (int nt = 0; nt < 8; ++nt){
            sa[nt][0] = __expf(sa[nt][0] - nm0); rs0 += sa[nt][0];
            sa[nt][1] = __expf(sa[nt][1] - nm0); rs0 += sa[nt][1];
            sa[nt][2] = __expf(sa[nt][2] - nm1); rs1 += sa[nt][2];
            sa[nt][3] = __expf(sa[nt][3] - nm1); rs1 += sa[nt][3];
        }
        rs0 += __shfl_xor_sync(0xffffffffu, rs0, 1);
        rs0 += __shfl_xor_sync(0xffffffffu, rs0, 2);
        rs1 += __shfl_xor_sync(0xffffffffu, rs1, 1);
        rs1 += __shfl_xor_sync(0xffffffffu, rs1, 2);
        l0 = l0*a0 + rs0; l1 = l1*a1 + rs1; m0 = nm0; m1 = nm1;
        #pragma unroll
        for (int nt = 0; nt < 8; ++nt){ oa[nt][0]*=a0; oa[nt][1]*=a0; oa[nt][2]*=a1; oa[nt][3]*=a1; }
        uint32_t pa[4][4];
        #pragma unroll
        for (int kf = 0; kf < 4; ++kf){
            pa[kf][0] = packh2(sa[2*kf][0],   sa[2*kf][1]);
            pa[kf][1] = packh2(sa[2*kf][2],   sa[2*kf][3]);
            pa[kf][2] = packh2(sa[2*kf+1][0], sa[2*kf+1][1]);
            pa[kf][3] = packh2(sa[2*kf+1][2], sa[2*kf+1][3]);
        }
        #pragma unroll
        for (int kf = 0; kf < 4; ++kf){
            #pragma unroll
            for (int nf2 = 0; nf2 < 4; ++nf2){
                uint32_t r[4];
                ldsm4t(r, sptr(&Vs[cur][(kf*16 + (lane&15))*72 + nf2*16 + (lane>>4)*8]));
                uint32_t blo[2] = {r[0], r[1]}, bhi[2] = {r[2], r[3]};
                mma16816(oa[nf2*2],   pa[kf], blo);
                mma16816(oa[nf2*2+1], pa[kf], bhi);
            }
        }
    }

    float il0 = 1.f / l0, il1 = 1.f / l1;
    int rlo = q0 + w*16 + (lane>>2);
    #pragma unroll
    for (int nt = 0; nt < 8; ++nt){
        int c = h*64 + nt*8 + (lane&3)*2;
        *(__half2*)(o + ((long)b*S_ + rlo)*D_ + c)     = __floats2half2_rn(oa[nt][0]*il0, oa[nt][1]*il0);
        *(__half2*)(o + ((long)b*S_ + rlo + 8)*D_ + c) = __floats2half2_rn(oa[nt][2]*il1, oa[nt][3]*il1);
    }
}

// ---------------- MoE routing ----------------
__global__ __launch_bounds__(256) void moe_init_k(){
    int i = blockIdx.x*256 + threadIdx.x;
    if (i < MROWS) g_gather[i] = -1;
    if (i < E_){ g_counts[i] = 0; g_cursor[i] = 0; }
}

__global__ __launch_bounds__(256) void gate_k(const float* __restrict__ xf, const float* __restrict__ gw){
    int n = blockIdx.x;
    int tid = threadIdx.x, w = tid >> 5, lane = tid & 31;
    const float* xr = xf + (long)n * D_;
    const float* gr = gw + (long)w * D_;
    float s = 0.f;
    for (int d = lane; d < D_; d += 32) s += xr[d] * gr[d];
    #pragma unroll
    for (int o = 16; o; o >>= 1) s += __shfl_xor_sync(0xffffffffu, s, o);
    __shared__ float sc[E_];
    if (lane == 0) sc[w] = s;
    __syncthreads();
    if (tid == 0){
        float mx = sc[0];
        for (int e = 1; e < E_; e++) mx = fmaxf(mx, sc[e]);
        float p[E_]; float sum = 0.f;
        for (int e = 0; e < E_; e++){ p[e] = expf(sc[e] - mx); sum += p[e]; }
        float inv = 1.f / sum;
        for (int e = 0; e < E_; e++) p[e] *= inv;
        int e0 = 0;
        for (int e = 1; e < E_; e++) if (p[e] > p[e0]) e0 = e;
        int e1 = (e0 == 0) ? 1 : 0;
        for (int e = 0; e < E_; e++){ if (e == e0) continue; if (p[e] > p[e1]) e1 = e; }
        float v0 = p[e0], v1 = p[e1];
        float wi = 1.f / (v0 + v1 + 1e-9f);
        g_tokE[2*n] = e0; g_tokE[2*n+1] = e1;
        g_tokW[2*n] = v0*wi; g_tokW[2*n+1] = v1*wi;
        atomicAdd(&g_counts[e0], 1);
        atomicAdd(&g_counts[e1], 1);
    }
}

__global__ void offsets_k(){
    if (threadIdx.x == 0){
        int acc = 0;
        for (int e = 0; e < E_; e++){ g_padbase[e] = acc; acc += ((g_counts[e] + 127) >> 7) << 7; }
        g_padbase[E_] = acc;
    }
    __syncthreads();
    int t = threadIdx.x;
    if (t < NTILES){
        int start = t*128, te = 0;
        if (start < g_padbase[E_]){
            for (int e = 0; e < E_; e++)
                if (start >= g_padbase[e] && start < g_padbase[e+1]) te = e;
        }
        g_tileE[t] = te;
    }
}

__global__ __launch_bounds__(256) void scatter_k(){
    int n = blockIdx.x*256 + threadIdx.x;
    if (n >= NTOK) return;
    #pragma unroll
    for (int kk = 0; kk < 2; kk++){
        int e = g_tokE[2*n + kk];
        int slot = atomicAdd(&g_cursor[e], 1);
        int pos = g_padbase[e] + slot;
        g_gather[pos] = n;
        g_tokPos[2*n + kk] = pos;
    }
}

__global__ __launch_bounds__(256) void combine_k(float* __restrict__ out){
    int i = blockIdx.x*256 + threadIdx.x;
    int n = i >> 10, d = i & 1023;
    float v = g_h[i] + g_sh[i];
    v += g_tokW[2*n]   * g_eo[(long)g_tokPos[2*n]  * D_ + d];
    v += g_tokW[2*n+1] * g_eo[(long)g_tokPos[2*n+1]* D_ + d];
    out[i] = v;
}

// ---------------- host orchestration ----------------
extern "C" void kernel_launch(void* const* d_in, const int* in_sizes, int n_in,
                              void* d_out, int out_size) {
    const float* x   = (const float*)d_in[0];
    const float* fc  = (const float*)d_in[1];
    const float* fs  = (const float*)d_in[2];
    const float* anw = (const float*)d_in[3];
    const float* fnw = (const float*)d_in[4];
    const float* wq  = (const float*)d_in[5];
    const float* wk  = (const float*)d_in[6];
    const float* wv  = (const float*)d_in[7];
    const float* wo  = (const float*)d_in[8];
    const float* gw  = (const float*)d_in[9];
    const float* ew1 = (const float*)d_in[10];
    const float* ew2 = (const float*)d_in[11];
    const float* ew3 = (const float*)d_in[12];
    const float* sw1 = (const float*)d_in[13];
    const float* sw2 = (const float*)d_in[14];
    const float* sw3 = (const float*)d_in[15];
    float* out = (float*)d_out;

    float *h,*xf,*sh,*eo;
    __half *qkvs,*xnh,*atth,*xfh,*th,*h1h;
    __half *wqkvh,*woh,*w13h,*sw2h,*ew13h,*ew2h;
    int *gath,*tileE;
    cudaGetSymbolAddress((void**)&h,    g_h);
    cudaGetSymbolAddress((void**)&xf,   g_xf);
    cudaGetSymbolAddress((void**)&sh,   g_sh);
    cudaGetSymbolAddress((void**)&eo,   g_eo);
    cudaGetSymbolAddress((void**)&qkvs, g_qkvs);
    cudaGetSymbolAddress((void**)&xnh,  g_xnh);
    cudaGetSymbolAddress((void**)&atth, g_atth);
    cudaGetSymbolAddress((void**)&xfh,  g_xfh);
    cudaGetSymbolAddress((void**)&th,   g_th);
    cudaGetSymbolAddress((void**)&h1h,  g_h1h);
    cudaGetSymbolAddress((void**)&wqkvh,g_wqkvh);
    cudaGetSymbolAddress((void**)&woh,  g_woh);
    cudaGetSymbolAddress((void**)&w13h, g_w13h);
    cudaGetSymbolAddress((void**)&sw2h, g_sw2h);
    cudaGetSymbolAddress((void**)&ew13h,g_ew13h);
    cudaGetSymbolAddress((void**)&ew2h, g_ew2h);
    cudaGetSymbolAddress((void**)&gath,  g_gather);
    cudaGetSymbolAddress((void**)&tileE, g_tileE);

    __half* qh = qkvs;
    __half* kh = qkvs + (long)NTOK*D_;
    __half* vh = qkvs + 2l*NTOK*D_;

    // opt-in dynamic smem for all hgemm instantiations
    cudaFuncSetAttribute(hgemm_k<float,0>,  cudaFuncAttributeMaxDynamicSharedMemorySize, GEMM_SMEM);
    cudaFuncSetAttribute(hgemm_k<float,1>,  cudaFuncAttributeMaxDynamicSharedMemorySize, GEMM_SMEM);
    cudaFuncSetAttribute(hgemm_k<__half,3>, cudaFuncAttributeMaxDynamicSharedMemorySize, GEMM_SMEM);
    cudaFuncSetAttribute(hgemm_k<__half,4>, cudaFuncAttributeMaxDynamicSharedMemorySize, GEMM_SMEM);

    // 0: merged weight conversion (with layout fusion)
    cvtall_k<<<(22*M1Q)/256, 256>>>(
        (const float4*)wq, (const float4*)wk, (const float4*)wv,
        (const float4*)wo, (const float4*)sw1, (const float4*)sw2, (const float4*)sw3,
        (const float4*)ew1, (const float4*)ew2, (const float4*)ew3);
    // 1: moe init
    moe_init_k<<<(MROWS + 255)/256, 256>>>();
    // 2: rmsnorm -> xnh
    rmsnorm_k<<<NTOK, 256>>>(x, anw, nullptr, xnh);
    // 3: QKV gemm + fused rope
    hgemm_k<__half,4><<<dim3(24,32), 256, GEMM_SMEM>>>(xnh, wqkvh, qkvs, nullptr, 1024, 3072,
                                                       nullptr, nullptr, 0, fc, fs);
    // 4: flash attention
    flash_h_k<<<dim3(S_/64, B_*H_), 128>>>(qh, kh, vh, atth);
    // 5: wo projection + residual  (<- ncu -s 5 lands here)
    hgemm_k<float,1><<<dim3(8,32), 256, GEMM_SMEM>>>(atth, woh, h, x, 1024, 1024,
                                                     nullptr, nullptr, 0, nullptr, nullptr);
    // 6: rmsnorm -> xf, xfh
    rmsnorm_k<<<NTOK, 256>>>(h, fnw, xf, xfh);
    // 7: fused shared FFN up
    hgemm_k<__half,3><<<dim3(16,32), 256, GEMM_SMEM>>>(xfh, w13h, th, nullptr, 1024, 2048,
                                                       nullptr, nullptr, 0, nullptr, nullptr);
    // 8: shared FFN down
    hgemm_k<float,0><<<dim3(8,32), 256, GEMM_SMEM>>>(th, sw2h, sh, nullptr, 1024, 1024,
                                                     nullptr, nullptr, 0, nullptr, nullptr);
    // 9-11: routing
    gate_k<<<NTOK, 256>>>(xf, gw);
    offsets_k<<<1, 128>>>();
    scatter_k<<<NTOK/256, 256>>>();
    // 12: fused MoE up (gathered)
    hgemm_k<__half,3><<<dim3(16,NTILES), 256, GEMM_SMEM>>>(xfh, ew13h, h1h, nullptr, 1024, 2048,
                                                           gath, tileE, 1024l*2048, nullptr, nullptr);
    // 13: MoE down
    hgemm_k<float,0><<<dim3(8,NTILES), 256, GEMM_SMEM>>>(h1h, ew2h, eo, nullptr, 1024, 1024,
                                                         nullptr, tileE, 1024l*1024, nullptr, nullptr);
    // 14: combine
    combine_k<<<(NTOK*D_)/256, 256>>>(out);
}